// round 2
// baseline (speedup 1.0000x reference)
#include <cuda_runtime.h>

#define HW_     36864
#define BB      16
#define CC      128
#define NPX     (BB*HW_)        /* 589824 */
#define NC_     5
#define SCALE_  0.125f
#define THRESH_ 0.7f
#define EPS_    1e-8f

// ---- scratch (allocation-free: device globals) ----
__device__ float g_down[NPX*16];      // lora_down output [B,HW,16] (scaled)
__device__ float g_mid [NPX*8];       // down @ A2        [B,HW,8]
__device__ float g_BA  [64];          // SCALE * B1 @ A2  [8,8]
__device__ float g_B1s [8*16];        // SCALE * B1
__device__ float g_num [BB*NC_*CC];
__device__ float g_xn2 [BB*CC];
__device__ float g_cn2 [NC_*CC];
__device__ float g_bestsim[BB];
__device__ int   g_bestidx[BB];

// ---------------------------------------------------------------------------
// K0: zero accumulators (graph-replay safe) + precompute
//     BA = SCALE * B1 @ A2   and   B1s = SCALE * B1
// ---------------------------------------------------------------------------
__global__ void k_init(const float* __restrict__ B1, const float* __restrict__ A2)
{
    int t = threadIdx.x;
    for (int i = t; i < BB*NC_*CC; i += 256) g_num[i] = 0.f;
    for (int i = t; i < BB*CC;     i += 256) g_xn2[i] = 0.f;
    for (int i = t; i < NC_*CC;    i += 256) g_cn2[i] = 0.f;
    if (t < 128) g_B1s[t] = B1[t] * SCALE_;
    if (t < 64) {
        int r = t >> 3, q = t & 7;
        float s = 0.f;
        #pragma unroll
        for (int j = 0; j < 16; j++) s += B1[r*16 + j] * A2[j*8 + q];
        g_BA[r*8 + q] = s * SCALE_;
    }
}

// ---------------------------------------------------------------------------
// K1: warp-per-pixel LoRA front end.  down = SCALE*(x@A1)@B1,  mid = down@A2
// ---------------------------------------------------------------------------
__global__ void k_lora(const float* __restrict__ x,
                       const float* __restrict__ A1)
{
    int lane = threadIdx.x & 31;
    int gw   = (blockIdx.x * blockDim.x + threadIdx.x) >> 5;
    int nw   = (gridDim.x * blockDim.x) >> 5;

    // per-lane constant slices
    float a1[4][8];
    #pragma unroll
    for (int i = 0; i < 4; i++)
        #pragma unroll
        for (int r = 0; r < 8; r++) a1[i][r] = A1[(lane*4 + i)*8 + r];
    int col  = lane & 15;
    int col8 = lane & 7;
    float bac[8], b1c[8];
    #pragma unroll
    for (int r = 0; r < 8; r++) {
        bac[r] = g_BA [r*8  + col8];   // column of SCALE*B1@A2
        b1c[r] = g_B1s[r*16 + col];    // column of SCALE*B1
    }

    for (int px = gw; px < NPX; px += nw) {
        float4 xv = ((const float4*)x)[(size_t)px*32 + lane];
        float tv[8];
        #pragma unroll
        for (int r = 0; r < 8; r++)
            tv[r] = xv.x*a1[0][r] + xv.y*a1[1][r] + xv.z*a1[2][r] + xv.w*a1[3][r];
        #pragma unroll
        for (int o = 16; o > 0; o >>= 1)
            #pragma unroll
            for (int r = 0; r < 8; r++)
                tv[r] += __shfl_xor_sync(0xffffffffu, tv[r], o);
        // mid (lanes 0..7):  tv @ (SCALE*B1@A2)
        float m = 0.f;
        #pragma unroll
        for (int r = 0; r < 8; r++) m += tv[r] * bac[r];
        if (lane < 8) g_mid[(size_t)px*8 + col8] = m;
        // down (lanes 0..15): tv @ (SCALE*B1)
        if (lane < 16) {
            float d = 0.f;
            #pragma unroll
            for (int r = 0; r < 8; r++) d += tv[r] * b1c[r];
            g_down[(size_t)px*16 + col] = d;
        }
    }
}

// ---------------------------------------------------------------------------
// K_cn: cache feature norms  cn2[n,c] = sum_hw cache[n,hw,c]^2
// ---------------------------------------------------------------------------
__global__ void k_cn(const float* __restrict__ cf)
{
    int c   = threadIdx.x;
    int n   = blockIdx.y;
    int hw0 = blockIdx.x * 288;
    float acc = 0.f;
    for (int h = 0; h < 288; h++) {
        float v = cf[((size_t)n*HW_ + hw0 + h)*CC + c];
        acc += v*v;
    }
    atomicAdd(&g_cn2[n*CC + c], acc);
}

// ---------------------------------------------------------------------------
// K_num: num[b,n,c] = sum_hw xl*cache,  xn2[b,c] = sum_hw xl^2
// xl recomputed from mid (smem-staged).  4 batches per block => cache slice
// reused 4x from L2 (whole cache fits in L2).
// ---------------------------------------------------------------------------
#define K2CHUNK 128
__global__ void k_num(const float* __restrict__ cf, const float* __restrict__ B2)
{
    __shared__ float4 mids[4][K2CHUNK*2];   // [b][hw*2 + part]
    int c   = threadIdx.x;                  // 0..127 = channel
    int hw0 = blockIdx.x * K2CHUNK;
    int b0  = blockIdx.y * 4;

    float b2c[8];
    #pragma unroll
    for (int r = 0; r < 8; r++) b2c[r] = B2[r*CC + c];

    const float4* midg = (const float4*)g_mid;
    for (int i = threadIdx.x; i < 4*K2CHUNK*2; i += 128) {
        int bb = i >> 8, rem = i & 255;
        mids[bb][rem] = midg[((size_t)(b0+bb)*HW_ + hw0)*2 + rem];
    }
    __syncthreads();

    float accn[4][5];
    float accx[4];
    #pragma unroll
    for (int bb = 0; bb < 4; bb++) {
        accx[bb] = 0.f;
        #pragma unroll
        for (int n = 0; n < 5; n++) accn[bb][n] = 0.f;
    }

    for (int h = 0; h < K2CHUNK; h++) {
        float xl[4];
        #pragma unroll
        for (int bb = 0; bb < 4; bb++) {
            float4 m0 = mids[bb][h*2], m1 = mids[bb][h*2+1];
            float v = m0.x*b2c[0] + m0.y*b2c[1] + m0.z*b2c[2] + m0.w*b2c[3]
                    + m1.x*b2c[4] + m1.y*b2c[5] + m1.z*b2c[6] + m1.w*b2c[7];
            xl[bb] = v * SCALE_;
            accx[bb] += xl[bb]*xl[bb];
        }
        #pragma unroll
        for (int n = 0; n < 5; n++) {
            float cv = cf[((size_t)n*HW_ + hw0 + h)*CC + c];
            #pragma unroll
            for (int bb = 0; bb < 4; bb++) accn[bb][n] += xl[bb]*cv;
        }
    }
    #pragma unroll
    for (int bb = 0; bb < 4; bb++) {
        #pragma unroll
        for (int n = 0; n < 5; n++)
            atomicAdd(&g_num[((b0+bb)*NC_ + n)*CC + c], accn[bb][n]);
        atomicAdd(&g_xn2[(b0+bb)*CC + c], accx[bb]);
    }
}

// ---------------------------------------------------------------------------
// K_sims: sims[b,n] = mean_c num / (max(xn,eps)*max(cn,eps)); argmax (first max)
// ---------------------------------------------------------------------------
__global__ void k_sims()
{
    __shared__ float s_sims[BB][NC_];
    int t = threadIdx.x;
    if (t < BB*NC_) {
        int b = t / NC_, n = t % NC_;
        float s = 0.f;
        for (int c = 0; c < CC; c++) {
            float xn = sqrtf(g_xn2[b*CC + c]);
            float cn = sqrtf(g_cn2[n*CC + c]);
            float denom = fmaxf(xn, EPS_) * fmaxf(cn, EPS_);
            s += g_num[(b*NC_ + n)*CC + c] / denom;
        }
        s_sims[b][n] = s * (1.0f/CC);
    }
    __syncthreads();
    if (t < BB) {
        float best = -1e30f; int bi = 0;
        #pragma unroll
        for (int n = 0; n < NC_; n++) {
            float v = s_sims[t][n];
            if (v > best) { best = v; bi = n; }
        }
        g_bestsim[t] = best;
        g_bestidx[t] = bi;
    }
}

// ---------------------------------------------------------------------------
// K_fuse: per (b, 64-pixel tile).
//   masked  : out = silu(concat(blend,down)@W1+b1)@W2+b2
//   unmasked: out = x_lora (recomputed from mid)
// px-major smem tiles; thread computes 4px x 8ch.
// ---------------------------------------------------------------------------
#define PK   148
#define TPX  64
#define SW1N (144*128)
#define SW2N (128*128)
#define SMEM_FLOATS (SW1N + SW2N + 1024 + TPX*8 + TPX*PK)

__global__ void __launch_bounds__(256, 1)
k_fuse(const float* __restrict__ cf,
       const float* __restrict__ W1, const float* __restrict__ b1,
       const float* __restrict__ W2, const float* __restrict__ b2,
       const float* __restrict__ B2, const float* __restrict__ cwp,
       float* __restrict__ out)
{
    extern __shared__ float sm[];
    float* sW1  = sm;                    // 18432
    float* sW2  = sW1 + SW1N;            // 16384
    float* sB2  = sW2 + SW2N;            // 1024
    float* sMid = sB2 + 1024;            // 512
    float* sT   = sMid + TPX*8;          // 64*148

    int b   = blockIdx.y;
    int hw0 = blockIdx.x * TPX;
    int tid = threadIdx.x;

    // mid + B2 into smem (both paths)
    if (tid < 128)
        ((float4*)sMid)[tid] = ((const float4*)(g_mid + ((size_t)b*HW_ + hw0)*8))[tid];
    ((float4*)sB2)[tid] = ((const float4*)B2)[tid];
    __syncthreads();

    bool masked = g_bestsim[b] > THRESH_;

    if (!masked) {
        float4* og = (float4*)(out + ((size_t)b*HW_ + hw0)*CC);
        for (int i = tid; i < TPX*32; i += 256) {
            int px = i >> 5, c = (i & 31) * 4;
            const float* mp = sMid + px*8;
            float4 r = make_float4(0.f,0.f,0.f,0.f);
            #pragma unroll
            for (int q = 0; q < 8; q++) {
                float mv = mp[q];
                float4 bv = *(const float4*)(sB2 + q*CC + c);
                r.x += mv*bv.x; r.y += mv*bv.y; r.z += mv*bv.z; r.w += mv*bv.w;
            }
            r.x *= SCALE_; r.y *= SCALE_; r.z *= SCALE_; r.w *= SCALE_;
            og[i] = r;
        }
        return;
    }

    // ---- masked path ----
    for (int i = tid; i < SW1N/4; i += 256) ((float4*)sW1)[i] = ((const float4*)W1)[i];
    for (int i = tid; i < SW2N/4; i += 256) ((float4*)sW2)[i] = ((const float4*)W2)[i];

    float cw   = 1.f / (1.f + __expf(-cwp[0]));
    float omcw = 1.f - cw;
    float cws  = cw * SCALE_;
    int   bi   = g_bestidx[b];
    const float* bestp = cf + ((size_t)bi*HW_ + hw0)*CC;

    // build in-tile (px-major, PK=148): cols 0..127 blend, 128..143 down
    #pragma unroll
    for (int pass = 0; pass < 8; pass++) {
        int px = pass*8 + (tid >> 5);
        int c  = (tid & 31) * 4;
        float4 bv = *(const float4*)(bestp + (size_t)px*CC + c);
        const float* mp = sMid + px*8;
        float4 xl = make_float4(0.f,0.f,0.f,0.f);
        #pragma unroll
        for (int q = 0; q < 8; q++) {
            float mv = mp[q];
            float4 b2v = *(const float4*)(sB2 + q*CC + c);
            xl.x += mv*b2v.x; xl.y += mv*b2v.y; xl.z += mv*b2v.z; xl.w += mv*b2v.w;
        }
        float4 bl;
        bl.x = cws*xl.x + omcw*bv.x;  bl.y = cws*xl.y + omcw*bv.y;
        bl.z = cws*xl.z + omcw*bv.z;  bl.w = cws*xl.w + omcw*bv.w;
        *(float4*)(sT + px*PK + c) = bl;
    }
    {
        int px = tid >> 2, r4 = (tid & 3) * 4;
        float4 dv = *(const float4*)(g_down + ((size_t)b*HW_ + hw0 + px)*16 + r4);
        *(float4*)(sT + px*PK + 128 + r4) = dv;
    }
    __syncthreads();

    // thread tile: 4px x 8ch
    int lane = tid & 31;
    int w    = tid >> 5;
    int p_base = (w >> 1)*16 + (lane >> 3)*4;
    int c_base = (w & 1)*64 + (lane & 7)*8;

    float bb1[8], bb2[8];
    #pragma unroll
    for (int j = 0; j < 8; j++) { bb1[j] = b1[c_base+j]; bb2[j] = b2[c_base+j]; }

    float acc[4][8];
    #pragma unroll
    for (int i = 0; i < 4; i++)
        #pragma unroll
        for (int j = 0; j < 8; j++) acc[i][j] = 0.f;

    const float* aT = sT + p_base*PK;
    #pragma unroll 4
    for (int k = 0; k < 144; k++) {
        float av[4];
        #pragma unroll
        for (int i = 0; i < 4; i++) av[i] = aT[i*PK + k];
        float4 w0 = *(const float4*)(sW1 + k*CC + c_base);
        float4 w1 = *(const float4*)(sW1 + k*CC + c_base + 4);
        float wv[8] = {w0.x,w0.y,w0.z,w0.w,w1.x,w1.y,w1.z,w1.w};
        #pragma unroll
        for (int i = 0; i < 4; i++)
            #pragma unroll
            for (int j = 0; j < 8; j++) acc[i][j] += av[i]*wv[j];
    }

    // silu(h) in registers
    float hreg[4][8];
    #pragma unroll
    for (int i = 0; i < 4; i++)
        #pragma unroll
        for (int j = 0; j < 8; j++) {
            float hv = acc[i][j] + bb1[j];
            hreg[i][j] = hv / (1.f + __expf(-hv));
        }
    __syncthreads();           // everyone done reading in-tile
    #pragma unroll
    for (int i = 0; i < 4; i++) {
        *(float4*)(sT + (p_base+i)*PK + c_base)     = make_float4(hreg[i][0],hreg[i][1],hreg[i][2],hreg[i][3]);
        *(float4*)(sT + (p_base+i)*PK + c_base + 4) = make_float4(hreg[i][4],hreg[i][5],hreg[i][6],hreg[i][7]);
    }
    __syncthreads();

    #pragma unroll
    for (int i = 0; i < 4; i++)
        #pragma unroll
        for (int j = 0; j < 8; j++) acc[i][j] = 0.f;

    #pragma unroll 4
    for (int k = 0; k < 128; k++) {
        float av[4];
        #pragma unroll
        for (int i = 0; i < 4; i++) av[i] = aT[i*PK + k];
        float4 w0 = *(const float4*)(sW2 + k*CC + c_base);
        float4 w1 = *(const float4*)(sW2 + k*CC + c_base + 4);
        float wv[8] = {w0.x,w0.y,w0.z,w0.w,w1.x,w1.y,w1.z,w1.w};
        #pragma unroll
        for (int i = 0; i < 4; i++)
            #pragma unroll
            for (int j = 0; j < 8; j++) acc[i][j] += av[i]*wv[j];
    }

    float* op = out + ((size_t)(b*HW_ + hw0) + p_base)*CC + c_base;
    #pragma unroll
    for (int i = 0; i < 4; i++) {
        *(float4*)(op + (size_t)i*CC)     = make_float4(acc[i][0]+bb2[0],acc[i][1]+bb2[1],acc[i][2]+bb2[2],acc[i][3]+bb2[3]);
        *(float4*)(op + (size_t)i*CC + 4) = make_float4(acc[i][4]+bb2[4],acc[i][5]+bb2[5],acc[i][6]+bb2[6],acc[i][7]+bb2[7]);
    }
}

// ---------------------------------------------------------------------------
extern "C" void kernel_launch(void* const* d_in, const int* in_sizes, int n_in,
                              void* d_out, int out_size)
{
    const float* x   = (const float*)d_in[0];
    const float* A1  = (const float*)d_in[1];
    const float* B1  = (const float*)d_in[2];
    const float* A2  = (const float*)d_in[3];
    const float* B2  = (const float*)d_in[4];
    const float* W1  = (const float*)d_in[5];
    const float* b1v = (const float*)d_in[6];
    const float* W2  = (const float*)d_in[7];
    const float* b2v = (const float*)d_in[8];
    const float* cw  = (const float*)d_in[9];
    const float* cf  = (const float*)d_in[10];
    float* out = (float*)d_out;

    cudaFuncSetAttribute(k_fuse, cudaFuncAttributeMaxDynamicSharedMemorySize,
                         SMEM_FLOATS * (int)sizeof(float));

    k_init  <<<1, 256>>>(B1, A2);
    k_lora  <<<2304, 256>>>(x, A1);
    k_cn    <<<dim3(128, NC_), 128>>>(cf);
    k_num   <<<dim3(HW_/K2CHUNK, 4), 128>>>(cf, B2);
    k_sims  <<<1, 128>>>();
    k_fuse  <<<dim3(HW_/TPX, BB), 256, SMEM_FLOATS * (int)sizeof(float)>>>(
                cf, W1, b1v, W2, b2v, B2, cw, out);
}

// round 3
// speedup vs baseline: 1.1375x; 1.1375x over previous
#include <cuda_runtime.h>

#define HW_     36864
#define BB      16
#define CC      128
#define NPX     (BB*HW_)        /* 589824 */
#define NC_     5
#define SCALE_  0.125f
#define THRESH_ 0.7f
#define EPS_    1e-8f

// packed fp32x2 helpers (FFMA2 — only reachable via PTX)
#define FMA2(d, a, b) asm("fma.rn.f32x2 %0, %1, %2, %0;" : "+l"(d) : "l"(a), "l"(b))
#define PACK2(d, s)   asm("mov.b64 %0, {%1, %1};" : "=l"(d) : "r"(s))
#define UNPK2(lo, hi, s) asm("mov.b64 {%0, %1}, %2;" : "=r"(lo), "=r"(hi) : "l"(s))

// ---- scratch (allocation-free: device globals) ----
__device__ float g_down[NPX*16];      // lora_down output [B,HW,16] (scaled)
__device__ float g_mid [NPX*8];       // down @ A2        [B,HW,8]
__device__ float g_BA  [64];          // SCALE * B1 @ A2  [8,8]
__device__ float g_B1s [8*16];        // SCALE * B1
__device__ float g_num [BB*NC_*CC];
__device__ float g_xn2 [BB*CC];
__device__ float g_cn2 [NC_*CC];
__device__ float g_bestsim[BB];
__device__ int   g_bestidx[BB];
__device__ int   g_mlist[BB];
__device__ int   g_mcount;
__device__ unsigned int g_ctr;

// ---------------------------------------------------------------------------
// K0: zero accumulators (graph-replay safe) + precompute
// ---------------------------------------------------------------------------
__global__ void k_init(const float* __restrict__ B1, const float* __restrict__ A2)
{
    int t = threadIdx.x;
    for (int i = t; i < BB*NC_*CC; i += 256) g_num[i] = 0.f;
    for (int i = t; i < BB*CC;     i += 256) g_xn2[i] = 0.f;
    for (int i = t; i < NC_*CC;    i += 256) g_cn2[i] = 0.f;
    if (t == 0) g_ctr = 0u;
    if (t < 128) g_B1s[t] = B1[t] * SCALE_;
    if (t < 64) {
        int r = t >> 3, q = t & 7;
        float s = 0.f;
        #pragma unroll
        for (int j = 0; j < 16; j++) s += B1[r*16 + j] * A2[j*8 + q];
        g_BA[r*8 + q] = s * SCALE_;
    }
}

// ---------------------------------------------------------------------------
// K1: warp-per-pixel LoRA front end.  down = SCALE*(x@A1)@B1,  mid = down@A2
// ---------------------------------------------------------------------------
__global__ void k_lora(const float* __restrict__ x,
                       const float* __restrict__ A1)
{
    int lane = threadIdx.x & 31;
    int gw   = (blockIdx.x * blockDim.x + threadIdx.x) >> 5;
    int nw   = (gridDim.x * blockDim.x) >> 5;

    float a1[4][8];
    #pragma unroll
    for (int i = 0; i < 4; i++)
        #pragma unroll
        for (int r = 0; r < 8; r++) a1[i][r] = A1[(lane*4 + i)*8 + r];
    int col  = lane & 15;
    int col8 = lane & 7;
    float bac[8], b1c[8];
    #pragma unroll
    for (int r = 0; r < 8; r++) {
        bac[r] = g_BA [r*8  + col8];
        b1c[r] = g_B1s[r*16 + col];
    }

    for (int px = gw; px < NPX; px += nw) {
        float4 xv = ((const float4*)x)[(size_t)px*32 + lane];
        float tv[8];
        #pragma unroll
        for (int r = 0; r < 8; r++)
            tv[r] = xv.x*a1[0][r] + xv.y*a1[1][r] + xv.z*a1[2][r] + xv.w*a1[3][r];
        #pragma unroll
        for (int o = 16; o > 0; o >>= 1)
            #pragma unroll
            for (int r = 0; r < 8; r++)
                tv[r] += __shfl_xor_sync(0xffffffffu, tv[r], o);
        float m = 0.f;
        #pragma unroll
        for (int r = 0; r < 8; r++) m += tv[r] * bac[r];
        if (lane < 8) g_mid[(size_t)px*8 + col8] = m;
        if (lane < 16) {
            float d = 0.f;
            #pragma unroll
            for (int r = 0; r < 8; r++) d += tv[r] * b1c[r];
            g_down[(size_t)px*16 + col] = d;
        }
    }
}

// ---------------------------------------------------------------------------
// K_cn: cache feature norms  cn2[n,c] = sum_hw cache[n,hw,c]^2
// ---------------------------------------------------------------------------
__global__ void k_cn(const float* __restrict__ cf)
{
    int c   = threadIdx.x;
    int n   = blockIdx.y;
    int hw0 = blockIdx.x * 96;
    float acc = 0.f;
    #pragma unroll 4
    for (int h = 0; h < 96; h++) {
        float v = cf[((size_t)n*HW_ + hw0 + h)*CC + c];
        acc += v*v;
    }
    atomicAdd(&g_cn2[n*CC + c], acc);
}

// ---------------------------------------------------------------------------
// K_num: num[b,n,c] = sum_hw xl*cache,  xn2[b,c] = sum_hw xl^2
// ---------------------------------------------------------------------------
#define K2CHUNK 64
__global__ void k_num(const float* __restrict__ cf, const float* __restrict__ B2)
{
    __shared__ float4 mids[4][K2CHUNK*2];   // [b][hw*2 + part]
    int c   = threadIdx.x;                  // 0..127 = channel
    int hw0 = blockIdx.x * K2CHUNK;
    int b0  = blockIdx.y * 4;

    float b2c[8];
    #pragma unroll
    for (int r = 0; r < 8; r++) b2c[r] = B2[r*CC + c];

    const float4* midg = (const float4*)g_mid;
    for (int i = threadIdx.x; i < 4*K2CHUNK*2; i += 128) {
        int bb = i / (K2CHUNK*2), rem = i % (K2CHUNK*2);
        mids[bb][rem] = midg[((size_t)(b0+bb)*HW_ + hw0)*2 + rem];
    }
    __syncthreads();

    float accn[4][5];
    float accx[4];
    #pragma unroll
    for (int bb = 0; bb < 4; bb++) {
        accx[bb] = 0.f;
        #pragma unroll
        for (int n = 0; n < 5; n++) accn[bb][n] = 0.f;
    }

    #pragma unroll 2
    for (int h = 0; h < K2CHUNK; h++) {
        float xl[4];
        #pragma unroll
        for (int bb = 0; bb < 4; bb++) {
            float4 m0 = mids[bb][h*2], m1 = mids[bb][h*2+1];
            float v = m0.x*b2c[0] + m0.y*b2c[1] + m0.z*b2c[2] + m0.w*b2c[3]
                    + m1.x*b2c[4] + m1.y*b2c[5] + m1.z*b2c[6] + m1.w*b2c[7];
            xl[bb] = v * SCALE_;
            accx[bb] += xl[bb]*xl[bb];
        }
        #pragma unroll
        for (int n = 0; n < 5; n++) {
            float cv = cf[((size_t)n*HW_ + hw0 + h)*CC + c];
            #pragma unroll
            for (int bb = 0; bb < 4; bb++) accn[bb][n] += xl[bb]*cv;
        }
    }
    #pragma unroll
    for (int bb = 0; bb < 4; bb++) {
        #pragma unroll
        for (int n = 0; n < 5; n++)
            atomicAdd(&g_num[((b0+bb)*NC_ + n)*CC + c], accn[bb][n]);
        atomicAdd(&g_xn2[(b0+bb)*CC + c], accx[bb]);
    }
}

// ---------------------------------------------------------------------------
// K_sims: sims + argmax + masked-batch list
// ---------------------------------------------------------------------------
__global__ void k_sims()
{
    __shared__ float s_sims[BB][NC_];
    int t = threadIdx.x;
    if (t < BB*NC_) {
        int b = t / NC_, n = t % NC_;
        float s = 0.f;
        for (int c = 0; c < CC; c++) {
            float xn = sqrtf(g_xn2[b*CC + c]);
            float cn = sqrtf(g_cn2[n*CC + c]);
            float denom = fmaxf(xn, EPS_) * fmaxf(cn, EPS_);
            s += g_num[(b*NC_ + n)*CC + c] / denom;
        }
        s_sims[b][n] = s * (1.0f/CC);
    }
    __syncthreads();
    if (t < BB) {
        float best = -1e30f; int bi = 0;
        #pragma unroll
        for (int n = 0; n < NC_; n++) {
            float v = s_sims[t][n];
            if (v > best) { best = v; bi = n; }
        }
        g_bestsim[t] = best;
        g_bestidx[t] = bi;
    }
    __syncthreads();
    if (t == 0) {
        int m = 0;
        #pragma unroll
        for (int b = 0; b < BB; b++)
            if (g_bestsim[b] > THRESH_) g_mlist[m++] = b;
        g_mcount = m;
    }
}

// ---------------------------------------------------------------------------
// K_xlora: unmasked batches — out = x_lora recomputed from mid. High occupancy.
// ---------------------------------------------------------------------------
__global__ void __launch_bounds__(256)
k_xlora(const float* __restrict__ B2, float* __restrict__ out)
{
    __shared__ float sMid[128*8];
    __shared__ float sB2[1024];
    int b = blockIdx.y;
    if (g_bestsim[b] > THRESH_) return;
    int hw0 = blockIdx.x * 128;
    int tid = threadIdx.x;

    ((float4*)sMid)[tid] = ((const float4*)(g_mid + ((size_t)b*HW_ + hw0)*8))[tid];
    if (tid < 256) ((float4*)sB2)[tid] = ((const float4*)B2)[tid];
    __syncthreads();

    float4* og = (float4*)(out + ((size_t)b*HW_ + hw0)*CC);
    for (int i = tid; i < 128*32; i += 256) {
        int px = i >> 5, c = (i & 31) * 4;
        const float* mp = sMid + px*8;
        float4 r = make_float4(0.f,0.f,0.f,0.f);
        #pragma unroll
        for (int q = 0; q < 8; q++) {
            float mv = mp[q];
            float4 bv = *(const float4*)(sB2 + q*CC + c);
            r.x += mv*bv.x; r.y += mv*bv.y; r.z += mv*bv.z; r.w += mv*bv.w;
        }
        r.x *= SCALE_; r.y *= SCALE_; r.z *= SCALE_; r.w *= SCALE_;
        og[i] = r;
    }
}

// ---------------------------------------------------------------------------
// K_fuse: PERSISTENT. 148 blocks, W1/W2 loaded once, tiles pulled from an
// atomic queue over masked batches only. GEMMs in packed fma.rn.f32x2.
// thread tile: 4px x 8ch (4 channel-pairs).
// ---------------------------------------------------------------------------
#define PK   148
#define TPX  64
#define SW1N (144*128)
#define SW2N (128*128)
#define SMEM_FLOATS (SW1N + SW2N + 1024 + TPX*8 + TPX*PK)

__global__ void __launch_bounds__(256, 1)
k_fuse(const float* __restrict__ cf,
       const float* __restrict__ W1, const float* __restrict__ b1,
       const float* __restrict__ W2, const float* __restrict__ b2,
       const float* __restrict__ B2, const float* __restrict__ cwp,
       float* __restrict__ out)
{
    extern __shared__ float sm[];
    float* sW1  = sm;                    // 18432
    float* sW2  = sW1 + SW1N;            // 16384
    float* sB2  = sW2 + SW2N;            // 1024
    float* sMid = sB2 + 1024;            // 512
    float* sT   = sMid + TPX*8;          // 64*148
    __shared__ int sIdx;

    int tid = threadIdx.x;

    // one-time loads
    for (int i = tid; i < SW1N/4; i += 256) ((float4*)sW1)[i] = ((const float4*)W1)[i];
    for (int i = tid; i < SW2N/4; i += 256) ((float4*)sW2)[i] = ((const float4*)W2)[i];
    ((float4*)sB2)[tid] = ((const float4*)B2)[tid];

    int   mcount = g_mcount;
    int   total  = mcount * (HW_/TPX);
    float cw     = 1.f / (1.f + __expf(-cwp[0]));
    float omcw   = 1.f - cw;
    float cws    = cw * SCALE_;

    int lane = tid & 31;
    int w    = tid >> 5;
    int p_base = (w >> 1)*16 + (lane >> 3)*4;
    int c_base = (w & 1)*64 + (lane & 7)*8;

    float bb1[8], bb2[8];
    #pragma unroll
    for (int j = 0; j < 8; j++) { bb1[j] = b1[c_base+j]; bb2[j] = b2[c_base+j]; }

    while (true) {
        if (tid == 0) sIdx = (int)atomicAdd(&g_ctr, 1u);
        __syncthreads();                 // also guards smem reuse across iters
        int idx = sIdx;
        if (idx >= total) break;

        int b   = g_mlist[idx / (HW_/TPX)];
        int hw0 = (idx % (HW_/TPX)) * TPX;
        int bi  = g_bestidx[b];
        const float* bestp = cf + ((size_t)bi*HW_ + hw0)*CC;

        if (tid < 128)
            ((float4*)sMid)[tid] = ((const float4*)(g_mid + ((size_t)b*HW_ + hw0)*8))[tid];
        __syncthreads();

        // build in-tile (px-major, PK=148): cols 0..127 blend, 128..143 down
        #pragma unroll
        for (int pass = 0; pass < 8; pass++) {
            int px = pass*8 + (tid >> 5);
            int c  = (tid & 31) * 4;
            float4 bv = *(const float4*)(bestp + (size_t)px*CC + c);
            const float* mp = sMid + px*8;
            float4 xl = make_float4(0.f,0.f,0.f,0.f);
            #pragma unroll
            for (int q = 0; q < 8; q++) {
                float mv = mp[q];
                float4 b2v = *(const float4*)(sB2 + q*CC + c);
                xl.x += mv*b2v.x; xl.y += mv*b2v.y; xl.z += mv*b2v.z; xl.w += mv*b2v.w;
            }
            float4 bl;
            bl.x = cws*xl.x + omcw*bv.x;  bl.y = cws*xl.y + omcw*bv.y;
            bl.z = cws*xl.z + omcw*bv.z;  bl.w = cws*xl.w + omcw*bv.w;
            *(float4*)(sT + px*PK + c) = bl;
        }
        {
            int px = tid >> 2, r4 = (tid & 3) * 4;
            float4 dv = *(const float4*)(g_down + ((size_t)b*HW_ + hw0 + px)*16 + r4);
            *(float4*)(sT + px*PK + 128 + r4) = dv;
        }
        __syncthreads();

        // ---- GEMM1: [4px x 8ch] over K=144, packed f32x2 ----
        unsigned long long acc2[4][4];
        #pragma unroll
        for (int i = 0; i < 4; i++)
            #pragma unroll
            for (int j = 0; j < 4; j++) acc2[i][j] = 0ull;

        const float* aT = sT + p_base*PK;
        #pragma unroll 4
        for (int k = 0; k < 144; k++) {
            unsigned long long av2[4];
            #pragma unroll
            for (int i = 0; i < 4; i++) {
                unsigned int u = __float_as_uint(aT[i*PK + k]);
                PACK2(av2[i], u);
            }
            ulonglong2 w01 = *(const ulonglong2*)(sW1 + k*CC + c_base);
            ulonglong2 w23 = *(const ulonglong2*)(sW1 + k*CC + c_base + 4);
            #pragma unroll
            for (int i = 0; i < 4; i++) {
                FMA2(acc2[i][0], av2[i], w01.x);
                FMA2(acc2[i][1], av2[i], w01.y);
                FMA2(acc2[i][2], av2[i], w23.x);
                FMA2(acc2[i][3], av2[i], w23.y);
            }
        }

        // silu(h) in registers
        float hreg[4][8];
        #pragma unroll
        for (int i = 0; i < 4; i++)
            #pragma unroll
            for (int j = 0; j < 4; j++) {
                unsigned int ulo, uhi;
                UNPK2(ulo, uhi, acc2[i][j]);
                float h0 = __uint_as_float(ulo) + bb1[2*j];
                float h1 = __uint_as_float(uhi) + bb1[2*j+1];
                hreg[i][2*j]   = h0 / (1.f + __expf(-h0));
                hreg[i][2*j+1] = h1 / (1.f + __expf(-h1));
            }
        __syncthreads();           // everyone done reading in-tile
        #pragma unroll
        for (int i = 0; i < 4; i++) {
            *(float4*)(sT + (p_base+i)*PK + c_base)     = make_float4(hreg[i][0],hreg[i][1],hreg[i][2],hreg[i][3]);
            *(float4*)(sT + (p_base+i)*PK + c_base + 4) = make_float4(hreg[i][4],hreg[i][5],hreg[i][6],hreg[i][7]);
        }
        __syncthreads();

        // ---- GEMM2: over K=128 ----
        #pragma unroll
        for (int i = 0; i < 4; i++)
            #pragma unroll
            for (int j = 0; j < 4; j++) acc2[i][j] = 0ull;

        #pragma unroll 4
        for (int k = 0; k < 128; k++) {
            unsigned long long av2[4];
            #pragma unroll
            for (int i = 0; i < 4; i++) {
                unsigned int u = __float_as_uint(aT[i*PK + k]);
                PACK2(av2[i], u);
            }
            ulonglong2 w01 = *(const ulonglong2*)(sW2 + k*CC + c_base);
            ulonglong2 w23 = *(const ulonglong2*)(sW2 + k*CC + c_base + 4);
            #pragma unroll
            for (int i = 0; i < 4; i++) {
                FMA2(acc2[i][0], av2[i], w01.x);
                FMA2(acc2[i][1], av2[i], w01.y);
                FMA2(acc2[i][2], av2[i], w23.x);
                FMA2(acc2[i][3], av2[i], w23.y);
            }
        }

        float* op = out + ((size_t)(b*HW_ + hw0) + p_base)*CC + c_base;
        #pragma unroll
        for (int i = 0; i < 4; i++) {
            float o[8];
            #pragma unroll
            for (int j = 0; j < 4; j++) {
                unsigned int ulo, uhi;
                UNPK2(ulo, uhi, acc2[i][j]);
                o[2*j]   = __uint_as_float(ulo) + bb2[2*j];
                o[2*j+1] = __uint_as_float(uhi) + bb2[2*j+1];
            }
            *(float4*)(op + (size_t)i*CC)     = make_float4(o[0],o[1],o[2],o[3]);
            *(float4*)(op + (size_t)i*CC + 4) = make_float4(o[4],o[5],o[6],o[7]);
        }
    }
}

// ---------------------------------------------------------------------------
extern "C" void kernel_launch(void* const* d_in, const int* in_sizes, int n_in,
                              void* d_out, int out_size)
{
    const float* x   = (const float*)d_in[0];
    const float* A1  = (const float*)d_in[1];
    const float* B1  = (const float*)d_in[2];
    const float* A2  = (const float*)d_in[3];
    const float* B2  = (const float*)d_in[4];
    const float* W1  = (const float*)d_in[5];
    const float* b1v = (const float*)d_in[6];
    const float* W2  = (const float*)d_in[7];
    const float* b2v = (const float*)d_in[8];
    const float* cw  = (const float*)d_in[9];
    const float* cf  = (const float*)d_in[10];
    float* out = (float*)d_out;

    cudaFuncSetAttribute(k_fuse, cudaFuncAttributeMaxDynamicSharedMemorySize,
                         SMEM_FLOATS * (int)sizeof(float));

    k_init  <<<1, 256>>>(B1, A2);
    k_lora  <<<2304, 256>>>(x, A1);
    k_cn    <<<dim3(HW_/96, NC_), 128>>>(cf);
    k_num   <<<dim3(HW_/K2CHUNK, 4), 128>>>(cf, B2);
    k_sims  <<<1, 128>>>();
    k_xlora <<<dim3(HW_/128, BB), 256>>>(B2, out);
    k_fuse  <<<148, 256, SMEM_FLOATS * (int)sizeof(float)>>>(
                cf, W1, b1v, W2, b2v, B2, cw, out);
}

// round 5
// speedup vs baseline: 1.5831x; 1.3918x over previous
#include <cuda_runtime.h>
#include <cstdint>

#define HW_     36864
#define BB      16
#define CC      128
#define NPX     (BB*HW_)        /* 589824 */
#define NC_     5
#define SCALE_  0.125f
#define THRESH_ 0.7f
#define EPS_    1e-8f

// ---------------------------------------------------------------------------
// tf32 helpers (legacy mma.sync path — works on plain sm_103 target)
// ---------------------------------------------------------------------------
__device__ __forceinline__ float tf32r(float x) {
    uint32_t u;
    asm("cvt.rna.tf32.f32 %0, %1;" : "=r"(u) : "f"(x));
    return __uint_as_float(u);
}
__device__ __forceinline__ void mma_tf32(float* c, float2 a01, float2 a23, float2 b) {
    asm volatile(
        "mma.sync.aligned.m16n8k8.row.col.f32.tf32.tf32.f32 "
        "{%0,%1,%2,%3}, {%4,%5,%6,%7}, {%8,%9}, {%0,%1,%2,%3};"
        : "+f"(c[0]), "+f"(c[1]), "+f"(c[2]), "+f"(c[3])
        : "r"(__float_as_uint(a01.x)), "r"(__float_as_uint(a23.x)),
          "r"(__float_as_uint(a01.y)), "r"(__float_as_uint(a23.y)),
          "r"(__float_as_uint(b.x)),   "r"(__float_as_uint(b.y)));
}
// interleaved position within an 8-group: pairs (t, t+4) adjacent
__device__ __forceinline__ int gpos(int k) {
    return (k & ~7) + 2*(k & 3) + ((k >> 2) & 1);
}

// ---- scratch (allocation-free: device globals) ----
__device__ float g_down[NPX*16];
__device__ float g_mid [NPX*8];
__device__ float g_BA  [64];
__device__ float g_B1s [8*16];
__device__ float g_num [BB*NC_*CC];
__device__ float g_xn2 [BB*CC];
__device__ float g_cn2 [NC_*CC];
__device__ float g_bestsim[BB];
__device__ int   g_bestidx[BB];
__device__ int   g_mlist[BB];
__device__ int   g_mcount;
__device__ unsigned int g_ctr;

// ---------------------------------------------------------------------------
__global__ void k_init(const float* __restrict__ B1, const float* __restrict__ A2)
{
    int t = threadIdx.x;
    for (int i = t; i < BB*NC_*CC; i += 256) g_num[i] = 0.f;
    for (int i = t; i < BB*CC;     i += 256) g_xn2[i] = 0.f;
    for (int i = t; i < NC_*CC;    i += 256) g_cn2[i] = 0.f;
    if (t == 0) g_ctr = 0u;
    if (t < 128) g_B1s[t] = B1[t] * SCALE_;
    if (t < 64) {
        int r = t >> 3, q = t & 7;
        float s = 0.f;
        #pragma unroll
        for (int j = 0; j < 16; j++) s += B1[r*16 + j] * A2[j*8 + q];
        g_BA[r*8 + q] = s * SCALE_;
    }
}

// ---------------------------------------------------------------------------
__global__ void k_lora(const float* __restrict__ x, const float* __restrict__ A1)
{
    int lane = threadIdx.x & 31;
    int gw   = (blockIdx.x * blockDim.x + threadIdx.x) >> 5;
    int nw   = (gridDim.x * blockDim.x) >> 5;

    float a1[4][8];
    #pragma unroll
    for (int i = 0; i < 4; i++)
        #pragma unroll
        for (int r = 0; r < 8; r++) a1[i][r] = A1[(lane*4 + i)*8 + r];
    int col  = lane & 15;
    int col8 = lane & 7;
    float bac[8], b1c[8];
    #pragma unroll
    for (int r = 0; r < 8; r++) {
        bac[r] = g_BA [r*8  + col8];
        b1c[r] = g_B1s[r*16 + col];
    }

    for (int px = gw; px < NPX; px += nw) {
        float4 xv = ((const float4*)x)[(size_t)px*32 + lane];
        float tv[8];
        #pragma unroll
        for (int r = 0; r < 8; r++)
            tv[r] = xv.x*a1[0][r] + xv.y*a1[1][r] + xv.z*a1[2][r] + xv.w*a1[3][r];
        #pragma unroll
        for (int o = 16; o > 0; o >>= 1)
            #pragma unroll
            for (int r = 0; r < 8; r++)
                tv[r] += __shfl_xor_sync(0xffffffffu, tv[r], o);
        float m = 0.f;
        #pragma unroll
        for (int r = 0; r < 8; r++) m += tv[r] * bac[r];
        if (lane < 8) g_mid[(size_t)px*8 + col8] = m;
        if (lane < 16) {
            float d = 0.f;
            #pragma unroll
            for (int r = 0; r < 8; r++) d += tv[r] * b1c[r];
            g_down[(size_t)px*16 + col] = d;
        }
    }
}

// ---------------------------------------------------------------------------
// K_num: num + xn2 (+cn2 from the y==0 slice)
// ---------------------------------------------------------------------------
#define K2CHUNK 64
__global__ void k_num(const float* __restrict__ cf, const float* __restrict__ B2)
{
    __shared__ float4 mids[4][K2CHUNK*2];
    int c   = threadIdx.x;
    int hw0 = blockIdx.x * K2CHUNK;
    int b0  = blockIdx.y * 4;
    bool do_cn = (blockIdx.y == 0);

    float b2c[8];
    #pragma unroll
    for (int r = 0; r < 8; r++) b2c[r] = B2[r*CC + c];

    const float4* midg = (const float4*)g_mid;
    for (int i = threadIdx.x; i < 4*K2CHUNK*2; i += 128) {
        int bb = i / (K2CHUNK*2), rem = i % (K2CHUNK*2);
        mids[bb][rem] = midg[((size_t)(b0+bb)*HW_ + hw0)*2 + rem];
    }
    __syncthreads();

    float accn[4][5], accx[4], accc[5];
    #pragma unroll
    for (int bb = 0; bb < 4; bb++) {
        accx[bb] = 0.f;
        #pragma unroll
        for (int n = 0; n < 5; n++) accn[bb][n] = 0.f;
    }
    #pragma unroll
    for (int n = 0; n < 5; n++) accc[n] = 0.f;

    #pragma unroll 2
    for (int h = 0; h < K2CHUNK; h++) {
        float xl[4];
        #pragma unroll
        for (int bb = 0; bb < 4; bb++) {
            float4 m0 = mids[bb][h*2], m1 = mids[bb][h*2+1];
            float v = m0.x*b2c[0] + m0.y*b2c[1] + m0.z*b2c[2] + m0.w*b2c[3]
                    + m1.x*b2c[4] + m1.y*b2c[5] + m1.z*b2c[6] + m1.w*b2c[7];
            xl[bb] = v * SCALE_;
            accx[bb] += xl[bb]*xl[bb];
        }
        #pragma unroll
        for (int n = 0; n < 5; n++) {
            float cv = cf[((size_t)n*HW_ + hw0 + h)*CC + c];
            accc[n] += cv*cv;
            #pragma unroll
            for (int bb = 0; bb < 4; bb++) accn[bb][n] += xl[bb]*cv;
        }
    }
    #pragma unroll
    for (int bb = 0; bb < 4; bb++) {
        #pragma unroll
        for (int n = 0; n < 5; n++)
            atomicAdd(&g_num[((b0+bb)*NC_ + n)*CC + c], accn[bb][n]);
        atomicAdd(&g_xn2[(b0+bb)*CC + c], accx[bb]);
    }
    if (do_cn) {
        #pragma unroll
        for (int n = 0; n < 5; n++) atomicAdd(&g_cn2[n*CC + c], accc[n]);
    }
}

// ---------------------------------------------------------------------------
__global__ void k_sims()
{
    __shared__ float s_sims[BB][NC_];
    int t = threadIdx.x;
    if (t < BB*NC_) {
        int b = t / NC_, n = t % NC_;
        float s = 0.f;
        for (int c = 0; c < CC; c++) {
            float xn = sqrtf(g_xn2[b*CC + c]);
            float cn = sqrtf(g_cn2[n*CC + c]);
            float denom = fmaxf(xn, EPS_) * fmaxf(cn, EPS_);
            s += g_num[(b*NC_ + n)*CC + c] / denom;
        }
        s_sims[b][n] = s * (1.0f/CC);
    }
    __syncthreads();
    if (t < BB) {
        float best = -1e30f; int bi = 0;
        #pragma unroll
        for (int n = 0; n < NC_; n++) {
            float v = s_sims[t][n];
            if (v > best) { best = v; bi = n; }
        }
        g_bestsim[t] = best;
        g_bestidx[t] = bi;
    }
    __syncthreads();
    if (t == 0) {
        int m = 0;
        #pragma unroll
        for (int b = 0; b < BB; b++)
            if (g_bestsim[b] > THRESH_) g_mlist[m++] = b;
        g_mcount = m;
    }
}

// ---------------------------------------------------------------------------
__global__ void __launch_bounds__(256)
k_xlora(const float* __restrict__ B2, float* __restrict__ out)
{
    __shared__ float sMid[128*8];
    __shared__ float sB2[1024];
    int b = blockIdx.y;
    if (g_bestsim[b] > THRESH_) return;
    int hw0 = blockIdx.x * 128;
    int tid = threadIdx.x;

    ((float4*)sMid)[tid] = ((const float4*)(g_mid + ((size_t)b*HW_ + hw0)*8))[tid];
    if (tid < 256) ((float4*)sB2)[tid] = ((const float4*)B2)[tid];
    __syncthreads();

    float4* og = (float4*)(out + ((size_t)b*HW_ + hw0)*CC);
    for (int i = tid; i < 128*32; i += 256) {
        int px = i >> 5, c = (i & 31) * 4;
        const float* mp = sMid + px*8;
        float4 r = make_float4(0.f,0.f,0.f,0.f);
        #pragma unroll
        for (int q = 0; q < 8; q++) {
            float mv = mp[q];
            float4 bv = *(const float4*)(sB2 + q*CC + c);
            r.x += mv*bv.x; r.y += mv*bv.y; r.z += mv*bv.z; r.w += mv*bv.w;
        }
        r.x *= SCALE_; r.y *= SCALE_; r.z *= SCALE_; r.w *= SCALE_;
        og[i] = r;
    }
}

// ---------------------------------------------------------------------------
// K_fuse: persistent; per 128px tile:
//   A = concat(best[128], mid[8], down[16])  (K=152, tf32, k-interleaved)
//   Wc1[n][k]: k<128 -> omcw*W1 ; 128..135 -> cws*(B2@W1a) ; 136..151 -> W1[128:144]
//   GEMM1 (mma.sync tf32) -> silu -> act2 -> GEMM2 with W2^T -> out + b2
// warp w owns output cols [w*16, w*16+16), all 128 px.
// ---------------------------------------------------------------------------
#define TPX     128
#define ST1     156       /* act1/Wc1 row stride (152 + pad) */
#define ST2     132       /* act2/W2t row stride (128 + pad) */
#define OFF_ACT 0
#define OFF_WC1 (128*ST1)
#define OFF_W2T (OFF_WC1 + 128*ST1)
#define OFF_BIA (OFF_W2T + 128*ST2)
#define SMEM_FL (OFF_BIA + 256)

__global__ void __launch_bounds__(256, 1)
k_fuse(const float* __restrict__ cf,
       const float* __restrict__ W1, const float* __restrict__ b1,
       const float* __restrict__ W2, const float* __restrict__ b2,
       const float* __restrict__ B2, const float* __restrict__ cwp,
       float* __restrict__ out)
{
    extern __shared__ float sm[];
    __shared__ int sIdx;
    int tid  = threadIdx.x;
    int wid  = tid >> 5;
    int lane = tid & 31;
    int gid  = lane >> 2;      // group id (row within frag)
    int tig  = lane & 3;       // thread in group
    int nbase = wid * 16;

    float cw   = 1.f / (1.f + __expf(-cwp[0]));
    float omcw = 1.f - cw;
    float cws  = cw * SCALE_;

    // ---- one-time weight staging (tf32-rounded, transposed, interleaved) ----
    for (int i = tid; i < 152*128; i += 256) {
        int k = i >> 7, n = i & 127;
        float v;
        if (k < 128) v = omcw * W1[k*CC + n];
        else if (k < 136) {
            int r = k - 128;
            float s = 0.f;
            for (int j = 0; j < 128; j++) s += B2[r*CC + j] * W1[j*CC + n];
            v = cws * s;
        } else v = W1[(k - 8)*CC + n];
        sm[OFF_WC1 + n*ST1 + gpos(k)] = tf32r(v);
    }
    for (int i = tid; i < 128*128; i += 256) {
        int k = i >> 7, n = i & 127;
        sm[OFF_W2T + n*ST2 + gpos(k)] = tf32r(W2[k*CC + n]);
    }
    if (tid < 128) {
        sm[OFF_BIA + tid]       = b1[tid];
        sm[OFF_BIA + 128 + tid] = b2[tid];
    }

    int mcount = g_mcount;
    int total  = mcount * (HW_/TPX);

    while (true) {
        if (tid == 0) sIdx = (int)atomicAdd(&g_ctr, 1u);
        __syncthreads();
        int idx = sIdx;
        if (idx >= total) break;

        int b   = g_mlist[idx / (HW_/TPX)];
        int hw0 = (idx % (HW_/TPX)) * TPX;
        int bi  = g_bestidx[b];

        // ---- build A tile (interleaved, tf32) ----
        const float4* bp = (const float4*)(cf + ((size_t)bi*HW_ + hw0)*CC);
        #pragma unroll 4
        for (int pass = 0; pass < 16; pass++) {
            int i  = pass*256 + tid;
            int px = i >> 5, c4 = (i & 31) * 4;
            float4 v = bp[i];
            float* dst = sm + OFF_ACT + px*ST1 + (c4 & ~7) + ((c4 >> 2) & 1);
            dst[0] = tf32r(v.x); dst[2] = tf32r(v.y);
            dst[4] = tf32r(v.z); dst[6] = tf32r(v.w);
        }
        {   // mid -> cols 128..135
            int px = tid >> 1, hf = tid & 1;
            float4 v = *(const float4*)(g_mid + ((size_t)b*HW_ + hw0 + px)*8 + hf*4);
            float* dst = sm + OFF_ACT + px*ST1 + 128 + hf;
            dst[0] = tf32r(v.x); dst[2] = tf32r(v.y);
            dst[4] = tf32r(v.z); dst[6] = tf32r(v.w);
        }
        #pragma unroll
        for (int j = 0; j < 2; j++) {  // down -> cols 136..151
            int i  = j*256 + tid;
            int px = i >> 2, q = i & 3;
            float4 v = *(const float4*)(g_down + ((size_t)b*HW_ + hw0 + px)*16 + q*4);
            float* dst = sm + OFF_ACT + px*ST1 + 136 + (q >> 1)*8 + (q & 1);
            dst[0] = tf32r(v.x); dst[2] = tf32r(v.y);
            dst[4] = tf32r(v.z); dst[6] = tf32r(v.w);
        }
        __syncthreads();

        // ---- GEMM1: 19 k-steps over K=152 ----
        float acc[8][2][4];
        #pragma unroll
        for (int mt = 0; mt < 8; mt++)
            #pragma unroll
            for (int nt = 0; nt < 2; nt++)
                #pragma unroll
                for (int v = 0; v < 4; v++) acc[mt][nt][v] = 0.f;

        #pragma unroll 1
        for (int ks = 0; ks < 19; ks++) {
            int kb = ks*8 + 2*tig;
            float2 bf0 = *(const float2*)(sm + OFF_WC1 + (nbase + gid)*ST1 + kb);
            float2 bf1 = *(const float2*)(sm + OFF_WC1 + (nbase + 8 + gid)*ST1 + kb);
            #pragma unroll
            for (int mt = 0; mt < 8; mt++) {
                float2 a01 = *(const float2*)(sm + OFF_ACT + (mt*16 + gid)*ST1 + kb);
                float2 a23 = *(const float2*)(sm + OFF_ACT + (mt*16 + 8 + gid)*ST1 + kb);
                mma_tf32(acc[mt][0], a01, a23, bf0);
                mma_tf32(acc[mt][1], a01, a23, bf1);
            }
        }
        __syncthreads();   // all warps done reading act1

        // ---- epilogue1: silu(h+b1) -> act2 (reuses act buffer, stride ST2) ----
        #pragma unroll
        for (int mt = 0; mt < 8; mt++)
            #pragma unroll
            for (int nt = 0; nt < 2; nt++)
                #pragma unroll
                for (int v = 0; v < 4; v++) {
                    int row = mt*16 + gid + ((v >> 1) << 3);
                    int col = nbase + nt*8 + 2*tig + (v & 1);
                    float h = acc[mt][nt][v] + sm[OFF_BIA + col];
                    float s = h / (1.f + __expf(-h));
                    sm[OFF_ACT + row*ST2 + gpos(col)] = tf32r(s);
                }
        __syncthreads();

        // ---- GEMM2: 16 k-steps over K=128 ----
        #pragma unroll
        for (int mt = 0; mt < 8; mt++)
            #pragma unroll
            for (int nt = 0; nt < 2; nt++)
                #pragma unroll
                for (int v = 0; v < 4; v++) acc[mt][nt][v] = 0.f;

        #pragma unroll 1
        for (int ks = 0; ks < 16; ks++) {
            int kb = ks*8 + 2*tig;
            float2 bf0 = *(const float2*)(sm + OFF_W2T + (nbase + gid)*ST2 + kb);
            float2 bf1 = *(const float2*)(sm + OFF_W2T + (nbase + 8 + gid)*ST2 + kb);
            #pragma unroll
            for (int mt = 0; mt < 8; mt++) {
                float2 a01 = *(const float2*)(sm + OFF_ACT + (mt*16 + gid)*ST2 + kb);
                float2 a23 = *(const float2*)(sm + OFF_ACT + (mt*16 + 8 + gid)*ST2 + kb);
                mma_tf32(acc[mt][0], a01, a23, bf0);
                mma_tf32(acc[mt][1], a01, a23, bf1);
            }
        }

        // ---- epilogue2: out = D + b2 ----
        #pragma unroll
        for (int mt = 0; mt < 8; mt++)
            #pragma unroll
            for (int nt = 0; nt < 2; nt++)
                #pragma unroll
                for (int h2 = 0; h2 < 2; h2++) {
                    int row = mt*16 + gid + h2*8;
                    int col = nbase + nt*8 + 2*tig;
                    float2 o;
                    o.x = acc[mt][nt][h2*2 + 0] + sm[OFF_BIA + 128 + col];
                    o.y = acc[mt][nt][h2*2 + 1] + sm[OFF_BIA + 128 + col + 1];
                    *(float2*)(out + ((size_t)b*HW_ + hw0 + row)*CC + col) = o;
                }
        __syncthreads();   // before next tile overwrites act
    }
}

// ---------------------------------------------------------------------------
extern "C" void kernel_launch(void* const* d_in, const int* in_sizes, int n_in,
                              void* d_out, int out_size)
{
    const float* x   = (const float*)d_in[0];
    const float* A1  = (const float*)d_in[1];
    const float* B1  = (const float*)d_in[2];
    const float* A2  = (const float*)d_in[3];
    const float* B2  = (const float*)d_in[4];
    const float* W1  = (const float*)d_in[5];
    const float* b1v = (const float*)d_in[6];
    const float* W2  = (const float*)d_in[7];
    const float* b2v = (const float*)d_in[8];
    const float* cw  = (const float*)d_in[9];
    const float* cf  = (const float*)d_in[10];
    float* out = (float*)d_out;

    cudaFuncSetAttribute(k_fuse, cudaFuncAttributeMaxDynamicSharedMemorySize,
                         SMEM_FL * (int)sizeof(float));

    k_init  <<<1, 256>>>(B1, A2);
    k_lora  <<<2304, 256>>>(x, A1);
    k_num   <<<dim3(HW_/K2CHUNK, 4), 128>>>(cf, B2);
    k_sims  <<<1, 128>>>();
    k_xlora <<<dim3(HW_/128, BB), 256>>>(B2, out);
    k_fuse  <<<148, 256, SMEM_FL * (int)sizeof(float)>>>(
                cf, W1, b1v, W2, b2v, B2, cw, out);
}

// round 6
// speedup vs baseline: 1.7227x; 1.0882x over previous
#include <cuda_runtime.h>
#include <cstdint>

#define HW_     36864
#define BB      16
#define CC      128
#define NPX     (BB*HW_)        /* 589824 */
#define NC_     5
#define SCALE_  0.125f
#define THRESH_ 0.7f
#define EPS_    1e-8f

// ---------------------------------------------------------------------------
// tf32 helpers (legacy mma.sync path — works on plain sm_103 target)
// ---------------------------------------------------------------------------
__device__ __forceinline__ float tf32r(float x) {
    uint32_t u;
    asm("cvt.rna.tf32.f32 %0, %1;" : "=r"(u) : "f"(x));
    return __uint_as_float(u);
}
__device__ __forceinline__ void mma_tf32(float* c, float2 a01, float2 a23, float2 b) {
    asm volatile(
        "mma.sync.aligned.m16n8k8.row.col.f32.tf32.tf32.f32 "
        "{%0,%1,%2,%3}, {%4,%5,%6,%7}, {%8,%9}, {%0,%1,%2,%3};"
        : "+f"(c[0]), "+f"(c[1]), "+f"(c[2]), "+f"(c[3])
        : "r"(__float_as_uint(a01.x)), "r"(__float_as_uint(a23.x)),
          "r"(__float_as_uint(a01.y)), "r"(__float_as_uint(a23.y)),
          "r"(__float_as_uint(b.x)),   "r"(__float_as_uint(b.y)));
}
// interleaved position within an 8-group: pairs (t, t+4) adjacent
__device__ __forceinline__ int gpos(int k) {
    return (k & ~7) + 2*(k & 3) + ((k >> 2) & 1);
}

// ---- scratch (allocation-free: device globals) ----
__device__ float g_down[NPX*16];
__device__ float g_mid [NPX*8];
__device__ float g_BA  [64];
__device__ float g_B1s [8*16];
__device__ float g_Mc  [128*24];      // tf32-rounded [c][j]: j<16 down-cols, j>=16 mid-cols
__device__ float g_num [BB*NC_*CC];
__device__ float g_xn2 [BB*CC];
__device__ float g_cn2 [NC_*CC];
__device__ float g_bestsim[BB];
__device__ int   g_bestidx[BB];
__device__ unsigned int g_ctr;

// ---------------------------------------------------------------------------
// K0: zero accumulators + precompute Mc = [A1@(S*B1) | A1@(S*B1@A2)]
// ---------------------------------------------------------------------------
__global__ void k_init(const float* __restrict__ B1, const float* __restrict__ A2,
                       const float* __restrict__ A1)
{
    int t = threadIdx.x;
    for (int i = t; i < BB*NC_*CC; i += 256) g_num[i] = 0.f;
    for (int i = t; i < BB*CC;     i += 256) g_xn2[i] = 0.f;
    for (int i = t; i < NC_*CC;    i += 256) g_cn2[i] = 0.f;
    if (t == 0) g_ctr = 0u;
    if (t < 128) g_B1s[t] = B1[t] * SCALE_;
    if (t < 64) {
        int r = t >> 3, q = t & 7;
        float s = 0.f;
        #pragma unroll
        for (int j = 0; j < 16; j++) s += B1[r*16 + j] * A2[j*8 + q];
        g_BA[r*8 + q] = s * SCALE_;
    }
    __syncthreads();
    for (int i = t; i < 128*24; i += 256) {
        int c = i / 24, j = i - c*24;
        float s = 0.f;
        #pragma unroll
        for (int r = 0; r < 8; r++) {
            float m = (j < 16) ? g_B1s[r*16 + j] : g_BA[r*8 + (j - 16)];
            s += A1[c*8 + r] * m;
        }
        g_Mc[i] = tf32r(s);
    }
}

// ---------------------------------------------------------------------------
// K1: [down|mid] = x @ Mc via tf32 HMMA. Block: 128px tile, 8 warps.
// ---------------------------------------------------------------------------
#define ST0 132
#define L_OFF_A  0
#define L_OFF_MC (128*ST0)
#define L_SMEM   (L_OFF_MC + 24*ST0)

__global__ void __launch_bounds__(256, 2)
k_lora(const float* __restrict__ x)
{
    extern __shared__ float sl[];
    int tid  = threadIdx.x;
    int wid  = tid >> 5;
    int lane = tid & 31;
    int gid  = lane >> 2;
    int tig  = lane & 3;
    size_t px0 = (size_t)blockIdx.x * 128;

    // stage Mc interleaved: [n][k]
    for (int i = tid; i < 24*128; i += 256) {
        int k = i >> 5, rem = i & 31;       // 128 k * 24 n? -> decode properly:
        (void)k; (void)rem;
    }
    for (int i = tid; i < 128*24; i += 256) {
        int c = i / 24, j = i - c*24;       // g_Mc[c*24+j]
        sl[L_OFF_MC + j*ST0 + gpos(c)] = g_Mc[i];
    }
    // stage x tile row-major (tf32-rounded), STS.128
    #pragma unroll 4
    for (int pass = 0; pass < 16; pass++) {
        int i  = pass*256 + tid;
        int px = i >> 5, c4 = (i & 31) * 4;
        float4 v = *(const float4*)(x + (px0 + px)*CC + c4);
        float4 o;
        o.x = tf32r(v.x); o.y = tf32r(v.y); o.z = tf32r(v.z); o.w = tf32r(v.w);
        *(float4*)(sl + L_OFF_A + px*ST0 + c4) = o;
    }
    __syncthreads();

    float acc[3][4];
    #pragma unroll
    for (int nt = 0; nt < 3; nt++)
        #pragma unroll
        for (int v = 0; v < 4; v++) acc[nt][v] = 0.f;

    const float* Ar0 = sl + L_OFF_A + (wid*16 + gid)*ST0;
    const float* Ar1 = Ar0 + 8*ST0;
    #pragma unroll
    for (int ks = 0; ks < 16; ks++) {
        int k0 = ks*8 + tig;
        float2 a01 = make_float2(Ar0[k0], Ar0[k0+4]);
        float2 a23 = make_float2(Ar1[k0], Ar1[k0+4]);
        #pragma unroll
        for (int nt = 0; nt < 3; nt++) {
            float2 b = *(const float2*)(sl + L_OFF_MC + (nt*8 + gid)*ST0 + ks*8 + 2*tig);
            mma_tf32(acc[nt], a01, a23, b);
        }
    }

    #pragma unroll
    for (int nt = 0; nt < 3; nt++)
        #pragma unroll
        for (int h2 = 0; h2 < 2; h2++) {
            size_t px = px0 + wid*16 + gid + h2*8;
            float2 o = make_float2(acc[nt][2*h2], acc[nt][2*h2+1]);
            if (nt < 2) *(float2*)(g_down + px*16 + nt*8 + 2*tig) = o;
            else        *(float2*)(g_mid  + px*8  + 2*tig)        = o;
        }
}

// ---------------------------------------------------------------------------
// K_num: num + xn2 (+cn2 from the y==0 slice)
// ---------------------------------------------------------------------------
#define K2CHUNK 64
__global__ void k_num(const float* __restrict__ cf, const float* __restrict__ B2)
{
    __shared__ float4 mids[4][K2CHUNK*2];
    int c   = threadIdx.x;
    int hw0 = blockIdx.x * K2CHUNK;
    int b0  = blockIdx.y * 4;
    bool do_cn = (blockIdx.y == 0);

    float b2c[8];
    #pragma unroll
    for (int r = 0; r < 8; r++) b2c[r] = B2[r*CC + c];

    const float4* midg = (const float4*)g_mid;
    for (int i = threadIdx.x; i < 4*K2CHUNK*2; i += 128) {
        int bb = i / (K2CHUNK*2), rem = i % (K2CHUNK*2);
        mids[bb][rem] = midg[((size_t)(b0+bb)*HW_ + hw0)*2 + rem];
    }
    __syncthreads();

    float accn[4][5], accx[4], accc[5];
    #pragma unroll
    for (int bb = 0; bb < 4; bb++) {
        accx[bb] = 0.f;
        #pragma unroll
        for (int n = 0; n < 5; n++) accn[bb][n] = 0.f;
    }
    #pragma unroll
    for (int n = 0; n < 5; n++) accc[n] = 0.f;

    #pragma unroll 2
    for (int h = 0; h < K2CHUNK; h++) {
        float xl[4];
        #pragma unroll
        for (int bb = 0; bb < 4; bb++) {
            float4 m0 = mids[bb][h*2], m1 = mids[bb][h*2+1];
            float v = m0.x*b2c[0] + m0.y*b2c[1] + m0.z*b2c[2] + m0.w*b2c[3]
                    + m1.x*b2c[4] + m1.y*b2c[5] + m1.z*b2c[6] + m1.w*b2c[7];
            xl[bb] = v * SCALE_;
            accx[bb] += xl[bb]*xl[bb];
        }
        #pragma unroll
        for (int n = 0; n < 5; n++) {
            float cv = cf[((size_t)n*HW_ + hw0 + h)*CC + c];
            accc[n] += cv*cv;
            #pragma unroll
            for (int bb = 0; bb < 4; bb++) accn[bb][n] += xl[bb]*cv;
        }
    }
    #pragma unroll
    for (int bb = 0; bb < 4; bb++) {
        #pragma unroll
        for (int n = 0; n < 5; n++)
            atomicAdd(&g_num[((b0+bb)*NC_ + n)*CC + c], accn[bb][n]);
        atomicAdd(&g_xn2[(b0+bb)*CC + c], accx[bb]);
    }
    if (do_cn) {
        #pragma unroll
        for (int n = 0; n < 5; n++) atomicAdd(&g_cn2[n*CC + c], accc[n]);
    }
}

// ---------------------------------------------------------------------------
// K_sims: block b, warp n: parallel reduction
// ---------------------------------------------------------------------------
__global__ void k_sims()
{
    __shared__ float s_s[NC_];
    int t = threadIdx.x;
    int n = t >> 5, lane = t & 31;
    int b = blockIdx.x;
    if (n < NC_) {
        float s = 0.f;
        #pragma unroll
        for (int j = 0; j < 4; j++) {
            int c = lane + 32*j;
            float xn = sqrtf(g_xn2[b*CC + c]);
            float cn = sqrtf(g_cn2[n*CC + c]);
            s += g_num[(b*NC_ + n)*CC + c] / (fmaxf(xn, EPS_) * fmaxf(cn, EPS_));
        }
        #pragma unroll
        for (int o = 16; o > 0; o >>= 1) s += __shfl_xor_sync(0xffffffffu, s, o);
        if (lane == 0) s_s[n] = s * (1.0f/CC);
    }
    __syncthreads();
    if (t == 0) {
        float best = -1e30f; int bi = 0;
        #pragma unroll
        for (int k = 0; k < NC_; k++) {
            float v = s_s[k];
            if (v > best) { best = v; bi = k; }
        }
        g_bestsim[b] = best;
        g_bestidx[b] = bi;
    }
}

// ---------------------------------------------------------------------------
// K_xlora: thread-per-pixel, mid in regs, B2 broadcast
// ---------------------------------------------------------------------------
__global__ void __launch_bounds__(256)
k_xlora(const float* __restrict__ B2, float* __restrict__ out)
{
    __shared__ float sB2[1024];
    int b = blockIdx.y;
    if (g_bestsim[b] > THRESH_) return;
    int tid = threadIdx.x;
    size_t px = (size_t)b*HW_ + blockIdx.x*256 + tid;

    ((float4*)sB2)[tid] = ((const float4*)B2)[tid];
    float4 m0 = *(const float4*)(g_mid + px*8);
    float4 m1 = *(const float4*)(g_mid + px*8 + 4);
    __syncthreads();

    float4* og = (float4*)(out + px*CC);
    #pragma unroll 4
    for (int c4 = 0; c4 < 32; c4++) {
        float4 r = make_float4(0.f,0.f,0.f,0.f);
        const float* bq = sB2 + c4*4;
        #pragma unroll
        for (int q = 0; q < 8; q++) {
            float mv = (q < 4) ? ((q==0)?m0.x:(q==1)?m0.y:(q==2)?m0.z:m0.w)
                               : ((q==4)?m1.x:(q==5)?m1.y:(q==6)?m1.z:m1.w);
            float4 bv = *(const float4*)(bq + q*CC);
            r.x += mv*bv.x; r.y += mv*bv.y; r.z += mv*bv.z; r.w += mv*bv.w;
        }
        r.x *= SCALE_; r.y *= SCALE_; r.z *= SCALE_; r.w *= SCALE_;
        og[c4] = r;
    }
}

// ---------------------------------------------------------------------------
// K_fuse: persistent tf32 HMMA MLP (unchanged core; mlist built locally)
// ---------------------------------------------------------------------------
#define TPX     128
#define ST1     156
#define ST2     132
#define OFF_ACT 0
#define OFF_WC1 (128*ST1)
#define OFF_W2T (OFF_WC1 + 128*ST1)
#define OFF_BIA (OFF_W2T + 128*ST2)
#define SMEM_FL (OFF_BIA + 256)

__global__ void __launch_bounds__(256, 1)
k_fuse(const float* __restrict__ cf,
       const float* __restrict__ W1, const float* __restrict__ b1,
       const float* __restrict__ W2, const float* __restrict__ b2,
       const float* __restrict__ B2, const float* __restrict__ cwp,
       float* __restrict__ out)
{
    extern __shared__ float sm[];
    __shared__ int sIdx;
    __shared__ int s_ml[BB];
    __shared__ int s_mc;
    int tid  = threadIdx.x;
    int wid  = tid >> 5;
    int lane = tid & 31;
    int gid  = lane >> 2;
    int tig  = lane & 3;
    int nbase = wid * 16;

    float cw   = 1.f / (1.f + __expf(-cwp[0]));
    float omcw = 1.f - cw;
    float cws  = cw * SCALE_;

    if (tid == 0) {
        int m = 0;
        #pragma unroll
        for (int b = 0; b < BB; b++)
            if (g_bestsim[b] > THRESH_) s_ml[m++] = b;
        s_mc = m;
    }

    // ---- one-time weight staging ----
    for (int i = tid; i < 152*128; i += 256) {
        int k = i >> 7, n = i & 127;
        float v;
        if (k < 128) v = omcw * W1[k*CC + n];
        else if (k < 136) {
            int r = k - 128;
            float s = 0.f;
            for (int j = 0; j < 128; j++) s += B2[r*CC + j] * W1[j*CC + n];
            v = cws * s;
        } else v = W1[(k - 8)*CC + n];
        sm[OFF_WC1 + n*ST1 + gpos(k)] = tf32r(v);
    }
    for (int i = tid; i < 128*128; i += 256) {
        int k = i >> 7, n = i & 127;
        sm[OFF_W2T + n*ST2 + gpos(k)] = tf32r(W2[k*CC + n]);
    }
    if (tid < 128) {
        sm[OFF_BIA + tid]       = b1[tid];
        sm[OFF_BIA + 128 + tid] = b2[tid];
    }
    __syncthreads();
    int total = s_mc * (HW_/TPX);

    while (true) {
        if (tid == 0) sIdx = (int)atomicAdd(&g_ctr, 1u);
        __syncthreads();
        int idx = sIdx;
        if (idx >= total) break;

        int b   = s_ml[idx / (HW_/TPX)];
        int hw0 = (idx % (HW_/TPX)) * TPX;
        int bi  = g_bestidx[b];

        // ---- build A tile (interleaved, tf32) ----
        const float4* bp = (const float4*)(cf + ((size_t)bi*HW_ + hw0)*CC);
        #pragma unroll 4
        for (int pass = 0; pass < 16; pass++) {
            int i  = pass*256 + tid;
            int px = i >> 5, c4 = (i & 31) * 4;
            float4 v = bp[i];
            float* dst = sm + OFF_ACT + px*ST1 + (c4 & ~7) + ((c4 >> 2) & 1);
            dst[0] = tf32r(v.x); dst[2] = tf32r(v.y);
            dst[4] = tf32r(v.z); dst[6] = tf32r(v.w);
        }
        {   // mid -> cols 128..135
            int px = tid >> 1, hf = tid & 1;
            float4 v = *(const float4*)(g_mid + ((size_t)b*HW_ + hw0 + px)*8 + hf*4);
            float* dst = sm + OFF_ACT + px*ST1 + 128 + hf;
            dst[0] = tf32r(v.x); dst[2] = tf32r(v.y);
            dst[4] = tf32r(v.z); dst[6] = tf32r(v.w);
        }
        #pragma unroll
        for (int j = 0; j < 2; j++) {  // down -> cols 136..151
            int i  = j*256 + tid;
            int px = i >> 2, q = i & 3;
            float4 v = *(const float4*)(g_down + ((size_t)b*HW_ + hw0 + px)*16 + q*4);
            float* dst = sm + OFF_ACT + px*ST1 + 136 + (q >> 1)*8 + (q & 1);
            dst[0] = tf32r(v.x); dst[2] = tf32r(v.y);
            dst[4] = tf32r(v.z); dst[6] = tf32r(v.w);
        }
        __syncthreads();

        // ---- GEMM1: 19 k-steps over K=152 ----
        float acc[8][2][4];
        #pragma unroll
        for (int mt = 0; mt < 8; mt++)
            #pragma unroll
            for (int nt = 0; nt < 2; nt++)
                #pragma unroll
                for (int v = 0; v < 4; v++) acc[mt][nt][v] = 0.f;

        #pragma unroll 1
        for (int ks = 0; ks < 19; ks++) {
            int kb = ks*8 + 2*tig;
            float2 bf0 = *(const float2*)(sm + OFF_WC1 + (nbase + gid)*ST1 + kb);
            float2 bf1 = *(const float2*)(sm + OFF_WC1 + (nbase + 8 + gid)*ST1 + kb);
            #pragma unroll
            for (int mt = 0; mt < 8; mt++) {
                float2 a01 = *(const float2*)(sm + OFF_ACT + (mt*16 + gid)*ST1 + kb);
                float2 a23 = *(const float2*)(sm + OFF_ACT + (mt*16 + 8 + gid)*ST1 + kb);
                mma_tf32(acc[mt][0], a01, a23, bf0);
                mma_tf32(acc[mt][1], a01, a23, bf1);
            }
        }
        __syncthreads();

        // ---- epilogue1: silu(h+b1) -> act2 ----
        #pragma unroll
        for (int mt = 0; mt < 8; mt++)
            #pragma unroll
            for (int nt = 0; nt < 2; nt++)
                #pragma unroll
                for (int v = 0; v < 4; v++) {
                    int row = mt*16 + gid + ((v >> 1) << 3);
                    int col = nbase + nt*8 + 2*tig + (v & 1);
                    float h = acc[mt][nt][v] + sm[OFF_BIA + col];
                    float s = h / (1.f + __expf(-h));
                    sm[OFF_ACT + row*ST2 + gpos(col)] = tf32r(s);
                }
        __syncthreads();

        // ---- GEMM2: 16 k-steps over K=128 ----
        #pragma unroll
        for (int mt = 0; mt < 8; mt++)
            #pragma unroll
            for (int nt = 0; nt < 2; nt++)
                #pragma unroll
                for (int v = 0; v < 4; v++) acc[mt][nt][v] = 0.f;

        #pragma unroll 1
        for (int ks = 0; ks < 16; ks++) {
            int kb = ks*8 + 2*tig;
            float2 bf0 = *(const float2*)(sm + OFF_W2T + (nbase + gid)*ST2 + kb);
            float2 bf1 = *(const float2*)(sm + OFF_W2T + (nbase + 8 + gid)*ST2 + kb);
            #pragma unroll
            for (int mt = 0; mt < 8; mt++) {
                float2 a01 = *(const float2*)(sm + OFF_ACT + (mt*16 + gid)*ST2 + kb);
                float2 a23 = *(const float2*)(sm + OFF_ACT + (mt*16 + 8 + gid)*ST2 + kb);
                mma_tf32(acc[mt][0], a01, a23, bf0);
                mma_tf32(acc[mt][1], a01, a23, bf1);
            }
        }

        // ---- epilogue2: out = D + b2 ----
        #pragma unroll
        for (int mt = 0; mt < 8; mt++)
            #pragma unroll
            for (int nt = 0; nt < 2; nt++)
                #pragma unroll
                for (int h2 = 0; h2 < 2; h2++) {
                    int row = mt*16 + gid + h2*8;
                    int col = nbase + nt*8 + 2*tig;
                    float2 o;
                    o.x = acc[mt][nt][h2*2 + 0] + sm[OFF_BIA + 128 + col];
                    o.y = acc[mt][nt][h2*2 + 1] + sm[OFF_BIA + 128 + col + 1];
                    *(float2*)(out + ((size_t)b*HW_ + hw0 + row)*CC + col) = o;
                }
        __syncthreads();
    }
}

// ---------------------------------------------------------------------------
extern "C" void kernel_launch(void* const* d_in, const int* in_sizes, int n_in,
                              void* d_out, int out_size)
{
    const float* x   = (const float*)d_in[0];
    const float* A1  = (const float*)d_in[1];
    const float* B1  = (const float*)d_in[2];
    const float* A2  = (const float*)d_in[3];
    const float* B2  = (const float*)d_in[4];
    const float* W1  = (const float*)d_in[5];
    const float* b1v = (const float*)d_in[6];
    const float* W2  = (const float*)d_in[7];
    const float* b2v = (const float*)d_in[8];
    const float* cw  = (const float*)d_in[9];
    const float* cf  = (const float*)d_in[10];
    float* out = (float*)d_out;

    cudaFuncSetAttribute(k_fuse, cudaFuncAttributeMaxDynamicSharedMemorySize,
                         SMEM_FL * (int)sizeof(float));
    cudaFuncSetAttribute(k_lora, cudaFuncAttributeMaxDynamicSharedMemorySize,
                         L_SMEM * (int)sizeof(float));

    k_init  <<<1, 256>>>(B1, A2, A1);
    k_lora  <<<NPX/128, 256, L_SMEM * (int)sizeof(float)>>>(x);
    k_num   <<<dim3(HW_/K2CHUNK, 4), 128>>>(cf, B2);
    k_sims  <<<BB, 160>>>();
    k_xlora <<<dim3(HW_/256, BB), 256>>>(B2, out);
    k_fuse  <<<148, 256, SMEM_FL * (int)sizeof(float)>>>(
                cf, W1, b1v, W2, b2v, B2, cw, out);
}

// round 7
// speedup vs baseline: 1.7805x; 1.0335x over previous
#include <cuda_runtime.h>
#include <cstdint>

#define HW_     36864
#define BB      16
#define CC      128
#define NPX     (BB*HW_)        /* 589824 */
#define NC_     5
#define SCALE_  0.125f
#define THRESH_ 0.7f
#define EPS_    1e-8f

// ---------------------------------------------------------------------------
// tf32 + f32x2 helpers
// ---------------------------------------------------------------------------
__device__ __forceinline__ float tf32r(float x) {
    uint32_t u;
    asm("cvt.rna.tf32.f32 %0, %1;" : "=r"(u) : "f"(x));
    return __uint_as_float(u);
}
__device__ __forceinline__ void mma_tf32(float* c, float2 a01, float2 a23, float2 b) {
    asm volatile(
        "mma.sync.aligned.m16n8k8.row.col.f32.tf32.tf32.f32 "
        "{%0,%1,%2,%3}, {%4,%5,%6,%7}, {%8,%9}, {%0,%1,%2,%3};"
        : "+f"(c[0]), "+f"(c[1]), "+f"(c[2]), "+f"(c[3])
        : "r"(__float_as_uint(a01.x)), "r"(__float_as_uint(a23.x)),
          "r"(__float_as_uint(a01.y)), "r"(__float_as_uint(a23.y)),
          "r"(__float_as_uint(b.x)),   "r"(__float_as_uint(b.y)));
}
#define FMA2(d, a, b) asm("fma.rn.f32x2 %0, %1, %2, %0;" : "+l"(d) : "l"(a), "l"(b))
#define PACK2(d, s)   asm("mov.b64 %0, {%1, %1};" : "=l"(d) : "r"(s))
#define UNPK2(lo, hi, s) asm("mov.b64 {%0, %1}, %2;" : "=r"(lo), "=r"(hi) : "l"(s))
// interleaved position within an 8-group: pairs (t, t+4) adjacent
__device__ __forceinline__ int gpos(int k) {
    return (k & ~7) + 2*(k & 3) + ((k >> 2) & 1);
}

// ---- scratch (allocation-free: device globals) ----
__device__ float g_down[NPX*16];
__device__ float g_mid [NPX*8];
__device__ float g_BA  [64];
__device__ float g_B1s [8*16];
__device__ float g_McI [24*128];      // interleaved [n][gpos(k)] = Mc[k][n], tf32
__device__ float g_num [BB*NC_*CC];
__device__ float g_xn2 [BB*CC];
__device__ float g_cn2 [NC_*CC];
__device__ float g_bestsim[BB];
__device__ int   g_bestidx[BB];
__device__ unsigned int g_ctr;

// ---------------------------------------------------------------------------
// K0: zero accumulators + precompute McI = interleave([A1@(S*B1) | A1@(S*B1@A2)]^T)
// ---------------------------------------------------------------------------
__global__ void k_init(const float* __restrict__ B1, const float* __restrict__ A2,
                       const float* __restrict__ A1)
{
    int t = threadIdx.x;
    for (int i = t; i < BB*NC_*CC; i += 256) g_num[i] = 0.f;
    for (int i = t; i < BB*CC;     i += 256) g_xn2[i] = 0.f;
    for (int i = t; i < NC_*CC;    i += 256) g_cn2[i] = 0.f;
    if (t == 0) g_ctr = 0u;
    if (t < 128) g_B1s[t] = B1[t] * SCALE_;
    if (t < 64) {
        int r = t >> 3, q = t & 7;
        float s = 0.f;
        #pragma unroll
        for (int j = 0; j < 16; j++) s += B1[r*16 + j] * A2[j*8 + q];
        g_BA[r*8 + q] = s * SCALE_;
    }
    __syncthreads();
    for (int i = t; i < 24*128; i += 256) {
        int n = i >> 7, k = i & 127;
        float s = 0.f;
        #pragma unroll
        for (int r = 0; r < 8; r++) {
            float m = (n < 16) ? g_B1s[r*16 + n] : g_BA[r*8 + (n - 16)];
            s += A1[k*8 + r] * m;
        }
        g_McI[n*128 + gpos(k)] = tf32r(s);
    }
}

// ---------------------------------------------------------------------------
// K1: [down|mid] = x @ Mc via tf32 HMMA. Block: 128px tile, 8 warps.
// Mc fragments read straight from g_McI (L1-hot, 12KB).
// ---------------------------------------------------------------------------
#define ST0 132
#define L_SMEM (128*ST0)

__global__ void __launch_bounds__(256, 3)
k_lora(const float* __restrict__ x)
{
    extern __shared__ float sl[];
    int tid  = threadIdx.x;
    int wid  = tid >> 5;
    int lane = tid & 31;
    int gid  = lane >> 2;
    int tig  = lane & 3;
    size_t px0 = (size_t)blockIdx.x * 128;

    // stage x tile row-major (tf32-rounded), STS.128
    #pragma unroll 4
    for (int pass = 0; pass < 16; pass++) {
        int i  = pass*256 + tid;
        int px = i >> 5, c4 = (i & 31) * 4;
        float4 v = *(const float4*)(x + (px0 + px)*CC + c4);
        float4 o;
        o.x = tf32r(v.x); o.y = tf32r(v.y); o.z = tf32r(v.z); o.w = tf32r(v.w);
        *(float4*)(sl + px*ST0 + c4) = o;
    }
    __syncthreads();

    float acc[3][4];
    #pragma unroll
    for (int nt = 0; nt < 3; nt++)
        #pragma unroll
        for (int v = 0; v < 4; v++) acc[nt][v] = 0.f;

    const float* Ar0 = sl + (wid*16 + gid)*ST0;
    const float* Ar1 = Ar0 + 8*ST0;
    #pragma unroll
    for (int ks = 0; ks < 16; ks++) {
        int k0 = ks*8 + tig;
        float2 a01 = make_float2(Ar0[k0], Ar0[k0+4]);
        float2 a23 = make_float2(Ar1[k0], Ar1[k0+4]);
        #pragma unroll
        for (int nt = 0; nt < 3; nt++) {
            float2 b = __ldg((const float2*)(g_McI + (nt*8 + gid)*128 + ks*8 + 2*tig));
            mma_tf32(acc[nt], a01, a23, b);
        }
    }

    #pragma unroll
    for (int nt = 0; nt < 3; nt++)
        #pragma unroll
        for (int h2 = 0; h2 < 2; h2++) {
            size_t px = px0 + wid*16 + gid + h2*8;
            float2 o = make_float2(acc[nt][2*h2], acc[nt][2*h2+1]);
            if (nt < 2) *(float2*)(g_down + px*16 + nt*8 + 2*tig) = o;
            else        *(float2*)(g_mid  + px*8  + 2*tig)        = o;
        }
}

// ---------------------------------------------------------------------------
// K_num: num + xn2 (+cn2 from the y==0 slice). Packed f32x2 over batch pairs.
// mids staged interleaved: midp[pair][h][q] = {mid_b(2p), mid_b(2p+1)}
// ---------------------------------------------------------------------------
#define K2CHUNK 64
__global__ void k_num(const float* __restrict__ cf, const float* __restrict__ B2)
{
    __shared__ float2 midp[2][K2CHUNK][8];
    int c   = threadIdx.x;
    int hw0 = blockIdx.x * K2CHUNK;
    int b0  = blockIdx.y * 4;
    bool do_cn = (blockIdx.y == 0);

    // B2 column pre-scaled by SCALE, packed broadcast
    unsigned long long b2cc[8];
    #pragma unroll
    for (int r = 0; r < 8; r++) {
        uint32_t u = __float_as_uint(B2[r*CC + c] * SCALE_);
        PACK2(b2cc[r], u);
    }

    const float4* midg = (const float4*)g_mid;
    for (int i = threadIdx.x; i < 4*K2CHUNK*2; i += 128) {
        int bb = i / (K2CHUNK*2), rem = i % (K2CHUNK*2);
        int h = rem >> 1, part = rem & 1;
        float4 v = midg[((size_t)(b0+bb)*HW_ + hw0 + h)*2 + part];
        int p = bb >> 1, s = bb & 1;
        float* dst = (float*)&midp[p][h][part*4];
        dst[0*2 + s] = v.x; dst[1*2 + s] = v.y;
        dst[2*2 + s] = v.z; dst[3*2 + s] = v.w;
    }
    __syncthreads();

    unsigned long long accn2[2][5], accx2[2];
    float accc[5];
    #pragma unroll
    for (int p = 0; p < 2; p++) {
        accx2[p] = 0ull;
        #pragma unroll
        for (int n = 0; n < 5; n++) accn2[p][n] = 0ull;
    }
    #pragma unroll
    for (int n = 0; n < 5; n++) accc[n] = 0.f;

    #pragma unroll 2
    for (int h = 0; h < K2CHUNK; h++) {
        unsigned long long xl2[2];
        #pragma unroll
        for (int p = 0; p < 2; p++) {
            unsigned long long a = 0ull;
            const unsigned long long* mp = (const unsigned long long*)&midp[p][h][0];
            #pragma unroll
            for (int q = 0; q < 8; q++) FMA2(a, mp[q], b2cc[q]);
            xl2[p] = a;
            FMA2(accx2[p], a, a);
        }
        #pragma unroll
        for (int n = 0; n < 5; n++) {
            float cv = cf[((size_t)n*HW_ + hw0 + h)*CC + c];
            accc[n] += cv*cv;
            unsigned long long cvv;
            PACK2(cvv, __float_as_uint(cv));
            FMA2(accn2[0][n], xl2[0], cvv);
            FMA2(accn2[1][n], xl2[1], cvv);
        }
    }
    #pragma unroll
    for (int p = 0; p < 2; p++) {
        uint32_t lo, hi;
        #pragma unroll
        for (int n = 0; n < 5; n++) {
            UNPK2(lo, hi, accn2[p][n]);
            atomicAdd(&g_num[((b0+2*p  )*NC_ + n)*CC + c], __uint_as_float(lo));
            atomicAdd(&g_num[((b0+2*p+1)*NC_ + n)*CC + c], __uint_as_float(hi));
        }
        UNPK2(lo, hi, accx2[p]);
        atomicAdd(&g_xn2[(b0+2*p  )*CC + c], __uint_as_float(lo));
        atomicAdd(&g_xn2[(b0+2*p+1)*CC + c], __uint_as_float(hi));
    }
    if (do_cn) {
        #pragma unroll
        for (int n = 0; n < 5; n++) atomicAdd(&g_cn2[n*CC + c], accc[n]);
    }
}

// ---------------------------------------------------------------------------
// K_sims: block b, warp n: parallel reduction
// ---------------------------------------------------------------------------
__global__ void k_sims()
{
    __shared__ float s_s[NC_];
    int t = threadIdx.x;
    int n = t >> 5, lane = t & 31;
    int b = blockIdx.x;
    if (n < NC_) {
        float s = 0.f;
        #pragma unroll
        for (int j = 0; j < 4; j++) {
            int c = lane + 32*j;
            float xn = sqrtf(g_xn2[b*CC + c]);
            float cn = sqrtf(g_cn2[n*CC + c]);
            s += g_num[(b*NC_ + n)*CC + c] / (fmaxf(xn, EPS_) * fmaxf(cn, EPS_));
        }
        #pragma unroll
        for (int o = 16; o > 0; o >>= 1) s += __shfl_xor_sync(0xffffffffu, s, o);
        if (lane == 0) s_s[n] = s * (1.0f/CC);
    }
    __syncthreads();
    if (t == 0) {
        float best = -1e30f; int bi = 0;
        #pragma unroll
        for (int k = 0; k < NC_; k++) {
            float v = s_s[k];
            if (v > best) { best = v; bi = k; }
        }
        g_bestsim[b] = best;
        g_bestidx[b] = bi;
    }
}

// ---------------------------------------------------------------------------
// K_xlora: thread-per-pixel, mid in regs, B2 broadcast
// ---------------------------------------------------------------------------
__global__ void __launch_bounds__(256)
k_xlora(const float* __restrict__ B2, float* __restrict__ out)
{
    __shared__ float sB2[1024];
    int b = blockIdx.y;
    if (g_bestsim[b] > THRESH_) return;
    int tid = threadIdx.x;
    size_t px = (size_t)b*HW_ + blockIdx.x*256 + tid;

    ((float4*)sB2)[tid] = ((const float4*)B2)[tid];
    float4 m0 = *(const float4*)(g_mid + px*8);
    float4 m1 = *(const float4*)(g_mid + px*8 + 4);
    __syncthreads();

    float4* og = (float4*)(out + px*CC);
    #pragma unroll 4
    for (int c4 = 0; c4 < 32; c4++) {
        float4 r = make_float4(0.f,0.f,0.f,0.f);
        const float* bq = sB2 + c4*4;
        #pragma unroll
        for (int q = 0; q < 8; q++) {
            float mv = (q < 4) ? ((q==0)?m0.x:(q==1)?m0.y:(q==2)?m0.z:m0.w)
                               : ((q==4)?m1.x:(q==5)?m1.y:(q==6)?m1.z:m1.w);
            float4 bv = *(const float4*)(bq + q*CC);
            r.x += mv*bv.x; r.y += mv*bv.y; r.z += mv*bv.z; r.w += mv*bv.w;
        }
        r.x *= SCALE_; r.y *= SCALE_; r.z *= SCALE_; r.w *= SCALE_;
        og[c4] = r;
    }
}

// ---------------------------------------------------------------------------
// K_fuse: persistent tf32 HMMA MLP (unchanged core)
// ---------------------------------------------------------------------------
#define TPX     128
#define ST1     156
#define ST2     132
#define OFF_ACT 0
#define OFF_WC1 (128*ST1)
#define OFF_W2T (OFF_WC1 + 128*ST1)
#define OFF_BIA (OFF_W2T + 128*ST2)
#define SMEM_FL (OFF_BIA + 256)

__global__ void __launch_bounds__(256, 1)
k_fuse(const float* __restrict__ cf,
       const float* __restrict__ W1, const float* __restrict__ b1,
       const float* __restrict__ W2, const float* __restrict__ b2,
       const float* __restrict__ B2, const float* __restrict__ cwp,
       float* __restrict__ out)
{
    extern __shared__ float sm[];
    __shared__ int sIdx;
    __shared__ int s_ml[BB];
    __shared__ int s_mc;
    int tid  = threadIdx.x;
    int wid  = tid >> 5;
    int lane = tid & 31;
    int gid  = lane >> 2;
    int tig  = lane & 3;
    int nbase = wid * 16;

    float cw   = 1.f / (1.f + __expf(-cwp[0]));
    float omcw = 1.f - cw;
    float cws  = cw * SCALE_;

    if (tid == 0) {
        int m = 0;
        #pragma unroll
        for (int b = 0; b < BB; b++)
            if (g_bestsim[b] > THRESH_) s_ml[m++] = b;
        s_mc = m;
    }

    // ---- one-time weight staging ----
    for (int i = tid; i < 152*128; i += 256) {
        int k = i >> 7, n = i & 127;
        float v;
        if (k < 128) v = omcw * W1[k*CC + n];
        else if (k < 136) {
            int r = k - 128;
            float s = 0.f;
            for (int j = 0; j < 128; j++) s += B2[r*CC + j] * W1[j*CC + n];
            v = cws * s;
        } else v = W1[(k - 8)*CC + n];
        sm[OFF_WC1 + n*ST1 + gpos(k)] = tf32r(v);
    }
    for (int i = tid; i < 128*128; i += 256) {
        int k = i >> 7, n = i & 127;
        sm[OFF_W2T + n*ST2 + gpos(k)] = tf32r(W2[k*CC + n]);
    }
    if (tid < 128) {
        sm[OFF_BIA + tid]       = b1[tid];
        sm[OFF_BIA + 128 + tid] = b2[tid];
    }
    __syncthreads();
    int total = s_mc * (HW_/TPX);

    while (true) {
        if (tid == 0) sIdx = (int)atomicAdd(&g_ctr, 1u);
        __syncthreads();
        int idx = sIdx;
        if (idx >= total) break;

        int b   = s_ml[idx / (HW_/TPX)];
        int hw0 = (idx % (HW_/TPX)) * TPX;
        int bi  = g_bestidx[b];

        // ---- build A tile (interleaved, tf32) ----
        const float4* bp = (const float4*)(cf + ((size_t)bi*HW_ + hw0)*CC);
        #pragma unroll 4
        for (int pass = 0; pass < 16; pass++) {
            int i  = pass*256 + tid;
            int px = i >> 5, c4 = (i & 31) * 4;
            float4 v = bp[i];
            float* dst = sm + OFF_ACT + px*ST1 + (c4 & ~7) + ((c4 >> 2) & 1);
            dst[0] = tf32r(v.x); dst[2] = tf32r(v.y);
            dst[4] = tf32r(v.z); dst[6] = tf32r(v.w);
        }
        {   // mid -> cols 128..135
            int px = tid >> 1, hf = tid & 1;
            float4 v = *(const float4*)(g_mid + ((size_t)b*HW_ + hw0 + px)*8 + hf*4);
            float* dst = sm + OFF_ACT + px*ST1 + 128 + hf;
            dst[0] = tf32r(v.x); dst[2] = tf32r(v.y);
            dst[4] = tf32r(v.z); dst[6] = tf32r(v.w);
        }
        #pragma unroll
        for (int j = 0; j < 2; j++) {  // down -> cols 136..151
            int i  = j*256 + tid;
            int px = i >> 2, q = i & 3;
            float4 v = *(const float4*)(g_down + ((size_t)b*HW_ + hw0 + px)*16 + q*4);
            float* dst = sm + OFF_ACT + px*ST1 + 136 + (q >> 1)*8 + (q & 1);
            dst[0] = tf32r(v.x); dst[2] = tf32r(v.y);
            dst[4] = tf32r(v.z); dst[6] = tf32r(v.w);
        }
        __syncthreads();

        // ---- GEMM1: 19 k-steps over K=152 ----
        float acc[8][2][4];
        #pragma unroll
        for (int mt = 0; mt < 8; mt++)
            #pragma unroll
            for (int nt = 0; nt < 2; nt++)
                #pragma unroll
                for (int v = 0; v < 4; v++) acc[mt][nt][v] = 0.f;

        #pragma unroll 1
        for (int ks = 0; ks < 19; ks++) {
            int kb = ks*8 + 2*tig;
            float2 bf0 = *(const float2*)(sm + OFF_WC1 + (nbase + gid)*ST1 + kb);
            float2 bf1 = *(const float2*)(sm + OFF_WC1 + (nbase + 8 + gid)*ST1 + kb);
            #pragma unroll
            for (int mt = 0; mt < 8; mt++) {
                float2 a01 = *(const float2*)(sm + OFF_ACT + (mt*16 + gid)*ST1 + kb);
                float2 a23 = *(const float2*)(sm + OFF_ACT + (mt*16 + 8 + gid)*ST1 + kb);
                mma_tf32(acc[mt][0], a01, a23, bf0);
                mma_tf32(acc[mt][1], a01, a23, bf1);
            }
        }
        __syncthreads();

        // ---- epilogue1: silu(h+b1) -> act2 ----
        #pragma unroll
        for (int mt = 0; mt < 8; mt++)
            #pragma unroll
            for (int nt = 0; nt < 2; nt++)
                #pragma unroll
                for (int v = 0; v < 4; v++) {
                    int row = mt*16 + gid + ((v >> 1) << 3);
                    int col = nbase + nt*8 + 2*tig + (v & 1);
                    float h = acc[mt][nt][v] + sm[OFF_BIA + col];
                    float s = h / (1.f + __expf(-h));
                    sm[OFF_ACT + row*ST2 + gpos(col)] = tf32r(s);
                }
        __syncthreads();

        // ---- GEMM2: 16 k-steps over K=128 ----
        #pragma unroll
        for (int mt = 0; mt < 8; mt++)
            #pragma unroll
            for (int nt = 0; nt < 2; nt++)
                #pragma unroll
                for (int v = 0; v < 4; v++) acc[mt][nt][v] = 0.f;

        #pragma unroll 1
        for (int ks = 0; ks < 16; ks++) {
            int kb = ks*8 + 2*tig;
            float2 bf0 = *(const float2*)(sm + OFF_W2T + (nbase + gid)*ST2 + kb);
            float2 bf1 = *(const float2*)(sm + OFF_W2T + (nbase + 8 + gid)*ST2 + kb);
            #pragma unroll
            for (int mt = 0; mt < 8; mt++) {
                float2 a01 = *(const float2*)(sm + OFF_ACT + (mt*16 + gid)*ST2 + kb);
                float2 a23 = *(const float2*)(sm + OFF_ACT + (mt*16 + 8 + gid)*ST2 + kb);
                mma_tf32(acc[mt][0], a01, a23, bf0);
                mma_tf32(acc[mt][1], a01, a23, bf1);
            }
        }

        // ---- epilogue2: out = D + b2 ----
        #pragma unroll
        for (int mt = 0; mt < 8; mt++)
            #pragma unroll
            for (int nt = 0; nt < 2; nt++)
                #pragma unroll
                for (int h2 = 0; h2 < 2; h2++) {
                    int row = mt*16 + gid + h2*8;
                    int col = nbase + nt*8 + 2*tig;
                    float2 o;
                    o.x = acc[mt][nt][h2*2 + 0] + sm[OFF_BIA + 128 + col];
                    o.y = acc[mt][nt][h2*2 + 1] + sm[OFF_BIA + 128 + col + 1];
                    *(float2*)(out + ((size_t)b*HW_ + hw0 + row)*CC + col) = o;
                }
        __syncthreads();
    }
}

// ---------------------------------------------------------------------------
extern "C" void kernel_launch(void* const* d_in, const int* in_sizes, int n_in,
                              void* d_out, int out_size)
{
    const float* x   = (const float*)d_in[0];
    const float* A1  = (const float*)d_in[1];
    const float* B1  = (const float*)d_in[2];
    const float* A2  = (const float*)d_in[3];
    const float* B2  = (const float*)d_in[4];
    const float* W1  = (const float*)d_in[5];
    const float* b1v = (const float*)d_in[6];
    const float* W2  = (const float*)d_in[7];
    const float* b2v = (const float*)d_in[8];
    const float* cw  = (const float*)d_in[9];
    const float* cf  = (const float*)d_in[10];
    float* out = (float*)d_out;

    cudaFuncSetAttribute(k_fuse, cudaFuncAttributeMaxDynamicSharedMemorySize,
                         SMEM_FL * (int)sizeof(float));
    cudaFuncSetAttribute(k_lora, cudaFuncAttributeMaxDynamicSharedMemorySize,
                         L_SMEM * (int)sizeof(float));

    k_init  <<<1, 256>>>(B1, A2, A1);
    k_lora  <<<NPX/128, 256, L_SMEM * (int)sizeof(float)>>>(x);
    k_num   <<<dim3(HW_/K2CHUNK, 4), 128>>>(cf, B2);
    k_sims  <<<BB, 160>>>();
    k_xlora <<<dim3(HW_/256, BB), 256>>>(B2, out);
    k_fuse  <<<148, 256, SMEM_FL * (int)sizeof(float)>>>(
                cf, W1, b1v, W2, b2v, B2, cw, out);
}

// round 8
// speedup vs baseline: 1.7999x; 1.0109x over previous
#include <cuda_runtime.h>
#include <cstdint>

#define HW_     36864
#define BB      16
#define CC      128
#define NPX     (BB*HW_)        /* 589824 */
#define NC_     5
#define SCALE_  0.125f
#define THRESH_ 0.7f
#define EPS_    1e-8f

// ---------------------------------------------------------------------------
// tf32 + f32x2 helpers
// ---------------------------------------------------------------------------
__device__ __forceinline__ float tf32r(float x) {
    uint32_t u;
    asm("cvt.rna.tf32.f32 %0, %1;" : "=r"(u) : "f"(x));
    return __uint_as_float(u);
}
__device__ __forceinline__ void mma_tf32(float* c, float2 a01, float2 a23, float2 b) {
    asm volatile(
        "mma.sync.aligned.m16n8k8.row.col.f32.tf32.tf32.f32 "
        "{%0,%1,%2,%3}, {%4,%5,%6,%7}, {%8,%9}, {%0,%1,%2,%3};"
        : "+f"(c[0]), "+f"(c[1]), "+f"(c[2]), "+f"(c[3])
        : "r"(__float_as_uint(a01.x)), "r"(__float_as_uint(a23.x)),
          "r"(__float_as_uint(a01.y)), "r"(__float_as_uint(a23.y)),
          "r"(__float_as_uint(b.x)),   "r"(__float_as_uint(b.y)));
}
#define FMA2(d, a, b) asm("fma.rn.f32x2 %0, %1, %2, %0;" : "+l"(d) : "l"(a), "l"(b))
#define PACK2(d, s)   asm("mov.b64 %0, {%1, %1};" : "=l"(d) : "r"(s))
#define UNPK2(lo, hi, s) asm("mov.b64 {%0, %1}, %2;" : "=r"(lo), "=r"(hi) : "l"(s))
// interleaved position within an 8-group: pairs (t, t+4) adjacent
__device__ __forceinline__ int gpos(int k) {
    return (k & ~7) + 2*(k & 3) + ((k >> 2) & 1);
}

// ---- scratch (allocation-free: device globals) ----
__device__ float g_down[NPX*16];
__device__ float g_mid [NPX*8];
__device__ float g_BA  [64];
__device__ float g_B1s [8*16];
__device__ float g_McI [24*128];      // interleaved [n][gpos(k)] = Mc[k][n], tf32
__device__ float g_num [BB*NC_*CC];
__device__ float g_xn2 [BB*CC];
__device__ float g_cn2 [NC_*CC];
__device__ float g_bestsim[BB];
__device__ int   g_bestidx[BB];
__device__ unsigned int g_ctr;

// ---------------------------------------------------------------------------
// K0: zero accumulators + precompute McI
// ---------------------------------------------------------------------------
__global__ void k_init(const float* __restrict__ B1, const float* __restrict__ A2,
                       const float* __restrict__ A1)
{
    int t = threadIdx.x;
    for (int i = t; i < BB*NC_*CC; i += 256) g_num[i] = 0.f;
    for (int i = t; i < BB*CC;     i += 256) g_xn2[i] = 0.f;
    for (int i = t; i < NC_*CC;    i += 256) g_cn2[i] = 0.f;
    if (t == 0) g_ctr = 0u;
    if (t < 128) g_B1s[t] = B1[t] * SCALE_;
    if (t < 64) {
        int r = t >> 3, q = t & 7;
        float s = 0.f;
        #pragma unroll
        for (int j = 0; j < 16; j++) s += B1[r*16 + j] * A2[j*8 + q];
        g_BA[r*8 + q] = s * SCALE_;
    }
    __syncthreads();
    for (int i = t; i < 24*128; i += 256) {
        int n = i >> 7, k = i & 127;
        float s = 0.f;
        #pragma unroll
        for (int r = 0; r < 8; r++) {
            float m = (n < 16) ? g_B1s[r*16 + n] : g_BA[r*8 + (n - 16)];
            s += A1[k*8 + r] * m;
        }
        g_McI[n*128 + gpos(k)] = tf32r(s);
    }
}

// ---------------------------------------------------------------------------
// K1: [down|mid] = x @ Mc via tf32 HMMA. Block: 128px tile, 8 warps.
// ---------------------------------------------------------------------------
#define ST0 132
#define L_SMEM (128*ST0)

__global__ void __launch_bounds__(256, 3)
k_lora(const float* __restrict__ x)
{
    extern __shared__ float sl[];
    int tid  = threadIdx.x;
    int wid  = tid >> 5;
    int lane = tid & 31;
    int gid  = lane >> 2;
    int tig  = lane & 3;
    size_t px0 = (size_t)blockIdx.x * 128;

    #pragma unroll 4
    for (int pass = 0; pass < 16; pass++) {
        int i  = pass*256 + tid;
        int px = i >> 5, c4 = (i & 31) * 4;
        float4 v = *(const float4*)(x + (px0 + px)*CC + c4);
        float4 o;
        o.x = tf32r(v.x); o.y = tf32r(v.y); o.z = tf32r(v.z); o.w = tf32r(v.w);
        *(float4*)(sl + px*ST0 + c4) = o;
    }
    __syncthreads();

    float acc[3][4];
    #pragma unroll
    for (int nt = 0; nt < 3; nt++)
        #pragma unroll
        for (int v = 0; v < 4; v++) acc[nt][v] = 0.f;

    const float* Ar0 = sl + (wid*16 + gid)*ST0;
    const float* Ar1 = Ar0 + 8*ST0;
    #pragma unroll
    for (int ks = 0; ks < 16; ks++) {
        int k0 = ks*8 + tig;
        float2 a01 = make_float2(Ar0[k0], Ar0[k0+4]);
        float2 a23 = make_float2(Ar1[k0], Ar1[k0+4]);
        #pragma unroll
        for (int nt = 0; nt < 3; nt++) {
            float2 b = __ldg((const float2*)(g_McI + (nt*8 + gid)*128 + ks*8 + 2*tig));
            mma_tf32(acc[nt], a01, a23, b);
        }
    }

    #pragma unroll
    for (int nt = 0; nt < 3; nt++)
        #pragma unroll
        for (int h2 = 0; h2 < 2; h2++) {
            size_t px = px0 + wid*16 + gid + h2*8;
            float2 o = make_float2(acc[nt][2*h2], acc[nt][2*h2+1]);
            if (nt < 2) *(float2*)(g_down + px*16 + nt*8 + 2*tig) = o;
            else        *(float2*)(g_mid  + px*8  + 2*tig)        = o;
        }
}

// ---------------------------------------------------------------------------
// K_num: num + xn2 (+cn2 from the y==0 slice). Packed f32x2 over batch pairs.
// ---------------------------------------------------------------------------
#define K2CHUNK 64
__global__ void k_num(const float* __restrict__ cf, const float* __restrict__ B2)
{
    __shared__ float2 midp[2][K2CHUNK][8];
    int c   = threadIdx.x;
    int hw0 = blockIdx.x * K2CHUNK;
    int b0  = blockIdx.y * 4;
    bool do_cn = (blockIdx.y == 0);

    unsigned long long b2cc[8];
    #pragma unroll
    for (int r = 0; r < 8; r++) {
        uint32_t u = __float_as_uint(B2[r*CC + c] * SCALE_);
        PACK2(b2cc[r], u);
    }

    const float4* midg = (const float4*)g_mid;
    for (int i = threadIdx.x; i < 4*K2CHUNK*2; i += 128) {
        int bb = i / (K2CHUNK*2), rem = i % (K2CHUNK*2);
        int h = rem >> 1, part = rem & 1;
        float4 v = midg[((size_t)(b0+bb)*HW_ + hw0 + h)*2 + part];
        int p = bb >> 1, s = bb & 1;
        float* dst = (float*)&midp[p][h][part*4];
        dst[0*2 + s] = v.x; dst[1*2 + s] = v.y;
        dst[2*2 + s] = v.z; dst[3*2 + s] = v.w;
    }
    __syncthreads();

    unsigned long long accn2[2][5], accx2[2];
    float accc[5];
    #pragma unroll
    for (int p = 0; p < 2; p++) {
        accx2[p] = 0ull;
        #pragma unroll
        for (int n = 0; n < 5; n++) accn2[p][n] = 0ull;
    }
    #pragma unroll
    for (int n = 0; n < 5; n++) accc[n] = 0.f;

    #pragma unroll 2
    for (int h = 0; h < K2CHUNK; h++) {
        unsigned long long xl2[2];
        #pragma unroll
        for (int p = 0; p < 2; p++) {
            unsigned long long a = 0ull;
            const unsigned long long* mp = (const unsigned long long*)&midp[p][h][0];
            #pragma unroll
            for (int q = 0; q < 8; q++) FMA2(a, mp[q], b2cc[q]);
            xl2[p] = a;
            FMA2(accx2[p], a, a);
        }
        #pragma unroll
        for (int n = 0; n < 5; n++) {
            float cv = cf[((size_t)n*HW_ + hw0 + h)*CC + c];
            accc[n] += cv*cv;
            unsigned long long cvv;
            PACK2(cvv, __float_as_uint(cv));
            FMA2(accn2[0][n], xl2[0], cvv);
            FMA2(accn2[1][n], xl2[1], cvv);
        }
    }
    #pragma unroll
    for (int p = 0; p < 2; p++) {
        uint32_t lo, hi;
        #pragma unroll
        for (int n = 0; n < 5; n++) {
            UNPK2(lo, hi, accn2[p][n]);
            atomicAdd(&g_num[((b0+2*p  )*NC_ + n)*CC + c], __uint_as_float(lo));
            atomicAdd(&g_num[((b0+2*p+1)*NC_ + n)*CC + c], __uint_as_float(hi));
        }
        UNPK2(lo, hi, accx2[p]);
        atomicAdd(&g_xn2[(b0+2*p  )*CC + c], __uint_as_float(lo));
        atomicAdd(&g_xn2[(b0+2*p+1)*CC + c], __uint_as_float(hi));
    }
    if (do_cn) {
        #pragma unroll
        for (int n = 0; n < 5; n++) atomicAdd(&g_cn2[n*CC + c], accc[n]);
    }
}

// ---------------------------------------------------------------------------
// K_sims
// ---------------------------------------------------------------------------
__global__ void k_sims()
{
    __shared__ float s_s[NC_];
    int t = threadIdx.x;
    int n = t >> 5, lane = t & 31;
    int b = blockIdx.x;
    if (n < NC_) {
        float s = 0.f;
        #pragma unroll
        for (int j = 0; j < 4; j++) {
            int c = lane + 32*j;
            float xn = sqrtf(g_xn2[b*CC + c]);
            float cn = sqrtf(g_cn2[n*CC + c]);
            s += g_num[(b*NC_ + n)*CC + c] / (fmaxf(xn, EPS_) * fmaxf(cn, EPS_));
        }
        #pragma unroll
        for (int o = 16; o > 0; o >>= 1) s += __shfl_xor_sync(0xffffffffu, s, o);
        if (lane == 0) s_s[n] = s * (1.0f/CC);
    }
    __syncthreads();
    if (t == 0) {
        float best = -1e30f; int bi = 0;
        #pragma unroll
        for (int k = 0; k < NC_; k++) {
            float v = s_s[k];
            if (v > best) { best = v; bi = k; }
        }
        g_bestsim[b] = best;
        g_bestidx[b] = bi;
    }
}

// ---------------------------------------------------------------------------
// K_fuse: persistent; unified queue of MLP tiles (masked, 128px) and
// x_lora tiles (unmasked, 256px).
// ---------------------------------------------------------------------------
#define TPX     128
#define UPX     256
#define ST1     156
#define ST2     132
#define OFF_ACT 0
#define OFF_WC1 (128*ST1)
#define OFF_W2T (OFF_WC1 + 128*ST1)
#define OFF_BIA (OFF_W2T + 128*ST2)
#define SMEM_FL (OFF_BIA + 256)

__global__ void __launch_bounds__(256, 1)
k_fuse(const float* __restrict__ cf,
       const float* __restrict__ W1, const float* __restrict__ b1,
       const float* __restrict__ W2, const float* __restrict__ b2,
       const float* __restrict__ B2, const float* __restrict__ cwp,
       float* __restrict__ out)
{
    extern __shared__ float sm[];
    __shared__ int sIdx;
    __shared__ int s_ml[BB], s_ul[BB];
    __shared__ int s_mc;
    int tid  = threadIdx.x;
    int wid  = tid >> 5;
    int lane = tid & 31;
    int gid  = lane >> 2;
    int tig  = lane & 3;
    int nbase = wid * 16;

    float cw   = 1.f / (1.f + __expf(-cwp[0]));
    float omcw = 1.f - cw;
    float cws  = cw * SCALE_;

    if (tid == 0) {
        int m = 0, u = 0;
        #pragma unroll
        for (int b = 0; b < BB; b++) {
            if (g_bestsim[b] > THRESH_) s_ml[m++] = b;
            else                        s_ul[u++] = b;
        }
        s_mc = m;
    }

    // ---- one-time weight staging ----
    for (int i = tid; i < 152*128; i += 256) {
        int k = i >> 7, n = i & 127;
        float v;
        if (k < 128) v = omcw * W1[k*CC + n];
        else if (k < 136) {
            int r = k - 128;
            float s = 0.f;
            for (int j = 0; j < 128; j++) s += B2[r*CC + j] * W1[j*CC + n];
            v = cws * s;
        } else v = W1[(k - 8)*CC + n];
        sm[OFF_WC1 + n*ST1 + gpos(k)] = tf32r(v);
    }
    for (int i = tid; i < 128*128; i += 256) {
        int k = i >> 7, n = i & 127;
        sm[OFF_W2T + n*ST2 + gpos(k)] = tf32r(W2[k*CC + n]);
    }
    if (tid < 128) {
        sm[OFF_BIA + tid]       = b1[tid];
        sm[OFF_BIA + 128 + tid] = b2[tid];
    }
    __syncthreads();
    int mc     = s_mc;
    int totalM = mc * (HW_/TPX);
    int total  = totalM + (BB - mc) * (HW_/UPX);

    while (true) {
        if (tid == 0) sIdx = (int)atomicAdd(&g_ctr, 1u);
        __syncthreads();
        int idx = sIdx;
        if (idx >= total) break;

        if (idx >= totalM) {
            // ================= x_lora item (unmasked batch, 256 px) =========
            int j  = idx - totalM;
            int b  = s_ul[j / (HW_/UPX)];
            size_t px = (size_t)b*HW_ + (size_t)(j % (HW_/UPX))*UPX + tid;

            float4 m0 = *(const float4*)(g_mid + px*8);
            float4 m1 = *(const float4*)(g_mid + px*8 + 4);
            m0.x *= SCALE_; m0.y *= SCALE_; m0.z *= SCALE_; m0.w *= SCALE_;
            m1.x *= SCALE_; m1.y *= SCALE_; m1.z *= SCALE_; m1.w *= SCALE_;

            float4* og = (float4*)(out + px*CC);
            #pragma unroll 4
            for (int c4 = 0; c4 < 32; c4++) {
                float4 r = make_float4(0.f,0.f,0.f,0.f);
                const float* bq = B2 + c4*4;
                #pragma unroll
                for (int q = 0; q < 8; q++) {
                    float mv = (q < 4) ? ((q==0)?m0.x:(q==1)?m0.y:(q==2)?m0.z:m0.w)
                                       : ((q==4)?m1.x:(q==5)?m1.y:(q==6)?m1.z:m1.w);
                    float4 bv = __ldg((const float4*)(bq + q*CC));
                    r.x += mv*bv.x; r.y += mv*bv.y; r.z += mv*bv.z; r.w += mv*bv.w;
                }
                og[c4] = r;
            }
            continue;   // next queue item (sync at loop top)
        }

        // ================= MLP item (masked batch, 128 px) ==================
        int b   = s_ml[idx / (HW_/TPX)];
        int hw0 = (idx % (HW_/TPX)) * TPX;
        int bi  = g_bestidx[b];

        // ---- build A tile (interleaved, tf32) ----
        const float4* bp = (const float4*)(cf + ((size_t)bi*HW_ + hw0)*CC);
        #pragma unroll 4
        for (int pass = 0; pass < 16; pass++) {
            int i  = pass*256 + tid;
            int px = i >> 5, c4 = (i & 31) * 4;
            float4 v = bp[i];
            float* dst = sm + OFF_ACT + px*ST1 + (c4 & ~7) + ((c4 >> 2) & 1);
            dst[0] = tf32r(v.x); dst[2] = tf32r(v.y);
            dst[4] = tf32r(v.z); dst[6] = tf32r(v.w);
        }
        {   // mid -> cols 128..135
            int px = tid >> 1, hf = tid & 1;
            float4 v = *(const float4*)(g_mid + ((size_t)b*HW_ + hw0 + px)*8 + hf*4);
            float* dst = sm + OFF_ACT + px*ST1 + 128 + hf;
            dst[0] = tf32r(v.x); dst[2] = tf32r(v.y);
            dst[4] = tf32r(v.z); dst[6] = tf32r(v.w);
        }
        #pragma unroll
        for (int j = 0; j < 2; j++) {  // down -> cols 136..151
            int i  = j*256 + tid;
            int px = i >> 2, q = i & 3;
            float4 v = *(const float4*)(g_down + ((size_t)b*HW_ + hw0 + px)*16 + q*4);
            float* dst = sm + OFF_ACT + px*ST1 + 136 + (q >> 1)*8 + (q & 1);
            dst[0] = tf32r(v.x); dst[2] = tf32r(v.y);
            dst[4] = tf32r(v.z); dst[6] = tf32r(v.w);
        }
        __syncthreads();

        // ---- GEMM1: 19 k-steps over K=152 ----
        float acc[8][2][4];
        #pragma unroll
        for (int mt = 0; mt < 8; mt++)
            #pragma unroll
            for (int nt = 0; nt < 2; nt++)
                #pragma unroll
                for (int v = 0; v < 4; v++) acc[mt][nt][v] = 0.f;

        #pragma unroll 1
        for (int ks = 0; ks < 19; ks++) {
            int kb = ks*8 + 2*tig;
            float2 bf0 = *(const float2*)(sm + OFF_WC1 + (nbase + gid)*ST1 + kb);
            float2 bf1 = *(const float2*)(sm + OFF_WC1 + (nbase + 8 + gid)*ST1 + kb);
            #pragma unroll
            for (int mt = 0; mt < 8; mt++) {
                float2 a01 = *(const float2*)(sm + OFF_ACT + (mt*16 + gid)*ST1 + kb);
                float2 a23 = *(const float2*)(sm + OFF_ACT + (mt*16 + 8 + gid)*ST1 + kb);
                mma_tf32(acc[mt][0], a01, a23, bf0);
                mma_tf32(acc[mt][1], a01, a23, bf1);
            }
        }
        __syncthreads();

        // ---- epilogue1: silu(h+b1) -> act2 ----
        #pragma unroll
        for (int mt = 0; mt < 8; mt++)
            #pragma unroll
            for (int nt = 0; nt < 2; nt++)
                #pragma unroll
                for (int v = 0; v < 4; v++) {
                    int row = mt*16 + gid + ((v >> 1) << 3);
                    int col = nbase + nt*8 + 2*tig + (v & 1);
                    float h = acc[mt][nt][v] + sm[OFF_BIA + col];
                    float s = h / (1.f + __expf(-h));
                    sm[OFF_ACT + row*ST2 + gpos(col)] = tf32r(s);
                }
        __syncthreads();

        // ---- GEMM2: 16 k-steps over K=128 ----
        #pragma unroll
        for (int mt = 0; mt < 8; mt++)
            #pragma unroll
            for (int nt = 0; nt < 2; nt++)
                #pragma unroll
                for (int v = 0; v < 4; v++) acc[mt][nt][v] = 0.f;

        #pragma unroll 1
        for (int ks = 0; ks < 16; ks++) {
            int kb = ks*8 + 2*tig;
            float2 bf0 = *(const float2*)(sm + OFF_W2T + (nbase + gid)*ST2 + kb);
            float2 bf1 = *(const float2*)(sm + OFF_W2T + (nbase + 8 + gid)*ST2 + kb);
            #pragma unroll
            for (int mt = 0; mt < 8; mt++) {
                float2 a01 = *(const float2*)(sm + OFF_ACT + (mt*16 + gid)*ST2 + kb);
                float2 a23 = *(const float2*)(sm + OFF_ACT + (mt*16 + 8 + gid)*ST2 + kb);
                mma_tf32(acc[mt][0], a01, a23, bf0);
                mma_tf32(acc[mt][1], a01, a23, bf1);
            }
        }

        // ---- epilogue2: out = D + b2 ----
        #pragma unroll
        for (int mt = 0; mt < 8; mt++)
            #pragma unroll
            for (int nt = 0; nt < 2; nt++)
                #pragma unroll
                for (int h2 = 0; h2 < 2; h2++) {
                    int row = mt*16 + gid + h2*8;
                    int col = nbase + nt*8 + 2*tig;
                    float2 o;
                    o.x = acc[mt][nt][h2*2 + 0] + sm[OFF_BIA + 128 + col];
                    o.y = acc[mt][nt][h2*2 + 1] + sm[OFF_BIA + 128 + col + 1];
                    *(float2*)(out + ((size_t)b*HW_ + hw0 + row)*CC + col) = o;
                }
        __syncthreads();
    }
}

// ---------------------------------------------------------------------------
extern "C" void kernel_launch(void* const* d_in, const int* in_sizes, int n_in,
                              void* d_out, int out_size)
{
    const float* x   = (const float*)d_in[0];
    const float* A1  = (const float*)d_in[1];
    const float* B1  = (const float*)d_in[2];
    const float* A2  = (const float*)d_in[3];
    const float* B2  = (const float*)d_in[4];
    const float* W1  = (const float*)d_in[5];
    const float* b1v = (const float*)d_in[6];
    const float* W2  = (const float*)d_in[7];
    const float* b2v = (const float*)d_in[8];
    const float* cw  = (const float*)d_in[9];
    const float* cf  = (const float*)d_in[10];
    float* out = (float*)d_out;

    cudaFuncSetAttribute(k_fuse, cudaFuncAttributeMaxDynamicSharedMemorySize,
                         SMEM_FL * (int)sizeof(float));
    cudaFuncSetAttribute(k_lora, cudaFuncAttributeMaxDynamicSharedMemorySize,
                         L_SMEM * (int)sizeof(float));

    k_init  <<<1, 256>>>(B1, A2, A1);
    k_lora  <<<NPX/128, 256, L_SMEM * (int)sizeof(float)>>>(x);
    k_num   <<<dim3(HW_/K2CHUNK, 4), 128>>>(cf, B2);
    k_sims  <<<BB, 160>>>();
    k_fuse  <<<148, 256, SMEM_FL * (int)sizeof(float)>>>(
                cf, W1, b1v, W2, b2v, B2, cw, out);
}